// round 6
// baseline (speedup 1.0000x reference)
#include <cuda_runtime.h>
#include <cuda_bf16.h>
#include <math.h>
#include <stdint.h>

// ---------------- problem constants ----------------
#define BATCH 16
#define IMG   197
#define TXT   24
#define SEQ   222
#define DIM   768
#define NH    12
#define HD    64
#define NL    6
#define VOC   50257
#define FF    3072
#define MROWS (BATCH*SEQ)  // 3552
#define QKVW  (3*DIM)      // 2304
#define MPAD  3584         // 28 * 128
#define NPADV 50432        // 197 * 256
#define KMAX  3072

// ---------------- GEMM tiling ----------------
#define TKC   32                 // K per stage
#define ASTR  40                 // smem row stride in bf16 (80B -> conflict-free LDSM)
#define MIOFF (16*ASTR*2)        // 1280 B: 16 rows
#define MATSZ_A (128*ASTR*2)     // 10240 B

// ---------------- device scratch ----------------
__device__ float g_x   [MROWS*DIM];
__device__ float g_qkv [MROWS*QKVW];
__device__ float g_o   [MROWS*DIM];
__device__ float g_ff  [MROWS*FF];
__device__ float g_t   [MROWS*DIM];
__device__ float g_b   [QKVW];
__device__ __nv_bfloat16 g_ah [MPAD*KMAX];
__device__ __nv_bfloat16 g_al [MPAD*KMAX];
__device__ __nv_bfloat16 g_bth[(size_t)NPADV*DIM];
__device__ __nv_bfloat16 g_btl[(size_t)NPADV*DIM];
__device__ float g_logits[(size_t)MROWS*NPADV];

// ---------------- PTX helpers ----------------
__device__ __forceinline__ uint32_t s2u(const void* p) {
    uint32_t a;
    asm("{ .reg .u64 t; cvta.to.shared.u64 t, %1; cvt.u32.u64 %0, t; }" : "=r"(a) : "l"(p));
    return a;
}
#define CP16(dst, src)   asm volatile("cp.async.cg.shared.global [%0], [%1], 16;" :: "r"(dst), "l"(src))
#define CP_COMMIT()      asm volatile("cp.async.commit_group;" ::: "memory")
#define CP_WAIT(n)       asm volatile("cp.async.wait_group %0;" :: "n"(n) : "memory")

__device__ __forceinline__ void mma16816(float* c, const uint32_t* a, const uint32_t* b) {
    asm volatile(
        "mma.sync.aligned.m16n8k16.row.col.f32.bf16.bf16.f32 "
        "{%0,%1,%2,%3}, {%4,%5,%6,%7}, {%8,%9}, {%0,%1,%2,%3};"
        : "+f"(c[0]), "+f"(c[1]), "+f"(c[2]), "+f"(c[3])
        : "r"(a[0]), "r"(a[1]), "r"(a[2]), "r"(a[3]), "r"(b[0]), "r"(b[1]));
}
__device__ __forceinline__ void ldsm4(uint32_t* r, uint32_t addr) {
    asm volatile("ldmatrix.sync.aligned.m8n8.x4.shared.b16 {%0,%1,%2,%3}, [%4];"
                 : "=r"(r[0]), "=r"(r[1]), "=r"(r[2]), "=r"(r[3]) : "r"(addr));
}

// ---------------- embedding ----------------
__global__ void embed_kernel(const float* __restrict__ img, const int* __restrict__ tok,
                             const float* __restrict__ temb, const float* __restrict__ sep,
                             float* __restrict__ x)
{
    int row = blockIdx.x;
    int b = row / SEQ, s = row % SEQ;
    const float* src;
    if (s < IMG)       src = img + (size_t)(b*IMG + s)*DIM;
    else if (s == IMG) src = sep;
    else               src = temb + (size_t)tok[b*TXT + (s-IMG-1)] * DIM;
    float* dst = x + (size_t)row*DIM;
    for (int i = threadIdx.x; i < DIM; i += blockDim.x) dst[i] = src[i];
}

// ---------------- activation split ----------------
__global__ void a_convert(const float* __restrict__ src, int Ms, int K)
{
    size_t idx = (size_t)blockIdx.x*256 + threadIdx.x;
    if (idx >= (size_t)MPAD*K) return;
    int row = (int)(idx / K);
    float v = (row < Ms) ? src[idx] : 0.f;
    __nv_bfloat16 h = __float2bfloat16(v);
    g_ah[idx] = h;
    g_al[idx] = __float2bfloat16(v - __bfloat162float(h));
}

// ---------------- weight transpose+split ----------------
__global__ void wt_convert(const float* __restrict__ src, int K, int N)
{
    __shared__ float t[32][33];
    int n0 = blockIdx.x*32, k0 = blockIdx.y*32;
    int tx = threadIdx.x, ty = threadIdx.y;
    #pragma unroll
    for (int j = 0; j < 32; j += 8) {
        int n = n0 + tx;
        t[ty+j][tx] = (n < N) ? src[(size_t)(k0+ty+j)*N + n] : 0.f;
    }
    __syncthreads();
    #pragma unroll
    for (int j = 0; j < 32; j += 8) {
        int n = n0 + ty + j, k = k0 + tx;
        float v = t[tx][ty+j];
        __nv_bfloat16 h = __float2bfloat16(v);
        size_t o = (size_t)n*K + k;
        g_bth[o] = h;
        g_btl[o] = __float2bfloat16(v - __bfloat162float(h));
    }
}

// ---------------- QKV weight gather+split ----------------
__global__ void qkvw_convert(const float* __restrict__ Wq, const float* __restrict__ Wk,
                             const float* __restrict__ Wv,
                             const float* __restrict__ bq, const float* __restrict__ bk,
                             const float* __restrict__ bv)
{
    int idx = blockIdx.x*256 + threadIdx.x;
    if (idx < QKVW*DIM) {
        int c = idx / DIM, d = idx % DIM;
        int which = c / DIM, w2 = c % DIM;
        int h = w2 >> 6, e = w2 & 63;
        const float* W = (which == 0) ? Wq : (which == 1) ? Wk : Wv;
        float v = W[(size_t)h*DIM*HD + (size_t)d*HD + e];
        __nv_bfloat16 hh = __float2bfloat16(v);
        g_bth[idx] = hh;
        g_btl[idx] = __float2bfloat16(v - __bfloat162float(hh));
    }
    if (idx < QKVW) {
        int which = idx / DIM, cc = idx % DIM;
        const float* bb = (which == 0) ? bq : (which == 1) ? bk : bv;
        g_b[idx] = bb[cc];
    }
}

// ---------------- mma.sync bf16 3-pass GEMM, templated tile ----------------
// NI = n8-tiles per warp (4 -> CTA 128x128, 8 -> CTA 128x256). 8 warps as 2(m) x 4(n).
template<int NI, int NSTG, int MAXCTA>
__global__ __launch_bounds__(256, MAXCTA)
void gemm_mma(const __nv_bfloat16* __restrict__ Ah, const __nv_bfloat16* __restrict__ Al,
              const __nv_bfloat16* __restrict__ Bh, const __nv_bfloat16* __restrict__ Bl,
              const float* __restrict__ bias, float* __restrict__ C,
              int K, int ldc, int Nreal, int Mreal, int relu)
{
    constexpr int TN      = 32 * NI;
    constexpr int MATSZ_B = TN * ASTR * 2;
    constexpr int STSZ    = 2*MATSZ_A + 2*MATSZ_B;
    constexpr int CH      = (256 + 2*TN) * 4;     // 16B chunks per stage

    extern __shared__ char dsm[];
    const int tid = threadIdx.x;
    const int wid = tid >> 5, lane = tid & 31;
    const int m0 = blockIdx.x * 128, n0 = blockIdx.y * TN;
    const int wm = wid >> 2, wn = wid & 3;
    const int g = lane >> 2, t = lane & 3;
    const int nk = K / TKC;
    const uint32_t sb = s2u(dsm);

    const int lm = lane >> 3, lj = lane & 7;
    const uint32_t aLane = ((uint32_t)((wm*64 + (lm & 1)*8 + lj) * ASTR + ((lm >> 1) * 8))) * 2;
    const uint32_t bLane = ((uint32_t)((wn*8*NI + (lm >> 1)*8 + lj) * ASTR + ((lm & 1) * 8))) * 2;

    float acc[4][NI][4];
    #pragma unroll
    for (int mi = 0; mi < 4; mi++)
        #pragma unroll
        for (int ni = 0; ni < NI; ni++)
            #pragma unroll
            for (int r = 0; r < 4; r++) acc[mi][ni][r] = 0.f;

    auto load_stage = [&](int st, int kc) {
        int k0_ = kc * TKC;
        #pragma unroll 4
        for (int c = tid; c < CH; c += 256) {
            int r4 = c >> 2, c16 = c & 3;
            const __nv_bfloat16* sp; uint32_t moff; int r; int base;
            if (r4 < 128)            { sp = Ah; r = r4;          moff = 0;                   base = m0; }
            else if (r4 < 256)       { sp = Al; r = r4 - 128;    moff = MATSZ_A;             base = m0; }
            else if (r4 < 256 + TN)  { sp = Bh; r = r4 - 256;    moff = 2*MATSZ_A;           base = n0; }
            else                     { sp = Bl; r = r4 - 256-TN; moff = 2*MATSZ_A + MATSZ_B; base = n0; }
            const __nv_bfloat16* src = sp + (size_t)(base + r) * K + k0_ + c16*8;
            CP16(sb + st*STSZ + moff + (uint32_t)r*80 + c16*16, src);
        }
        CP_COMMIT();
    };

    for (int i = 0; i < NSTG - 1 && i < nk; i++) load_stage(i, i);

    for (int kc = 0; kc < nk; kc++) {
        if (kc + NSTG - 1 < nk) load_stage((kc + NSTG - 1) % NSTG, kc + NSTG - 1);
        int rem = nk - 1 - kc; if (rem > NSTG - 1) rem = NSTG - 1;
        if (rem == 0)      CP_WAIT(0);
        else if (rem == 1) CP_WAIT(1);
        else               CP_WAIT(2);
        __syncthreads();

        const uint32_t stg = sb + (kc % NSTG) * STSZ;
        const uint32_t aB = stg + aLane;
        const uint32_t bB = stg + 2*MATSZ_A + bLane;

        #pragma unroll
        for (int ks = 0; ks < 2; ks++) {
            const uint32_t kof = ks * 32;
            uint32_t af[16], bhf[2*NI], blf[2*NI];
            #pragma unroll
            for (int p = 0; p < NI/2; p++) {
                ldsm4(bhf + 4*p, bB + p*MIOFF + kof);
                ldsm4(blf + 4*p, bB + MATSZ_B + p*MIOFF + kof);
            }
            #pragma unroll
            for (int mi = 0; mi < 4; mi++) ldsm4(af + mi*4, aB + mi*MIOFF + kof);
            #pragma unroll
            for (int mi = 0; mi < 4; mi++)
                #pragma unroll
                for (int ni = 0; ni < NI; ni++)
                    mma16816(acc[mi][ni], af + mi*4, bhf + ni*2);
            #pragma unroll
            for (int mi = 0; mi < 4; mi++)
                #pragma unroll
                for (int ni = 0; ni < NI; ni++)
                    mma16816(acc[mi][ni], af + mi*4, blf + ni*2);
            #pragma unroll
            for (int mi = 0; mi < 4; mi++) ldsm4(af + mi*4, aB + MATSZ_A + mi*MIOFF + kof);
            #pragma unroll
            for (int mi = 0; mi < 4; mi++)
                #pragma unroll
                for (int ni = 0; ni < NI; ni++)
                    mma16816(acc[mi][ni], af + mi*4, bhf + ni*2);
        }
        __syncthreads();
    }

    // epilogue
    #pragma unroll
    for (int mi = 0; mi < 4; mi++) {
        int gm0 = m0 + wm*64 + mi*16 + g;
        #pragma unroll
        for (int ni = 0; ni < NI; ni++) {
            int gn = n0 + wn*8*NI + ni*8 + t*2;
            float bx = (gn     < Nreal) ? bias[gn]     : 0.f;
            float by = (gn + 1 < Nreal) ? bias[gn + 1] : 0.f;
            float c0 = acc[mi][ni][0] + bx, c1 = acc[mi][ni][1] + by;
            float c2 = acc[mi][ni][2] + bx, c3 = acc[mi][ni][3] + by;
            if (relu) {
                c0 = fmaxf(c0, 0.f); c1 = fmaxf(c1, 0.f);
                c2 = fmaxf(c2, 0.f); c3 = fmaxf(c3, 0.f);
            }
            if (gm0 < Mreal)
                *reinterpret_cast<float2*>(C + (size_t)gm0*ldc + gn) = make_float2(c0, c1);
            if (gm0 + 8 < Mreal)
                *reinterpret_cast<float2*>(C + (size_t)(gm0+8)*ldc + gn) = make_float2(c2, c3);
        }
    }
}

#define DSMEM8 (3 * (2*MATSZ_A + 2*(256*ASTR*2)))   // 184320
#define DSMEM4 (2 * (2*MATSZ_A + 2*(128*ASTR*2)))   // 81920

// ---------------- attention: 4-way q split per (b,h) ----------------
#define KSTR 65
__global__ void attn_kernel(const float* __restrict__ qkv,
                            const int* __restrict__ tmask,
                            float* __restrict__ o)
{
    int bh = blockIdx.x >> 2, z = blockIdx.x & 3;
    int b = bh / NH, h = bh % NH;
    extern __shared__ float sm[];
    float* ks = sm;
    float* vs = ks + SEQ*KSTR;
    float* qs = vs + SEQ*KSTR;
    float* sc = qs + 8*64;
    unsigned char* valid = (unsigned char*)(sc + 8*224);

    int tid = threadIdx.x, lane = tid & 31, w = tid >> 5;
    const float* base = qkv + (size_t)b * SEQ * QKVW;

    for (int i = tid; i < SEQ*HD; i += 256) {
        int t = i >> 6, e = i & 63;
        ks[t*KSTR + e] = base[(size_t)t*QKVW +   DIM + h*64 + e];
        vs[t*KSTR + e] = base[(size_t)t*QKVW + 2*DIM + h*64 + e];
    }
    for (int t = tid; t < SEQ; t += 256)
        valid[t] = (t < SEQ - TXT) ? 1 : (tmask[b*TXT + t - (SEQ-TXT)] != 0);
    __syncthreads();

    float* myq  = qs + w*64;
    float* mysc = sc + w*224;
    for (int s = (w << 2) + z; s < SEQ; s += 32) {
        myq[lane]      = base[(size_t)s*QKVW + h*64 + lane];
        myq[lane + 32] = base[(size_t)s*QKVW + h*64 + lane + 32];
        __syncwarp();

        float lmax = -INFINITY;
        for (int t = lane; t <= s; t += 32) {
            float d = -INFINITY;
            if (valid[t]) {
                d = 0.f;
                #pragma unroll
                for (int e = 0; e < 64; e++) d += myq[e] * ks[t*KSTR + e];
                d *= 0.125f;
            }
            mysc[t] = d;
            lmax = fmaxf(lmax, d);
        }
        #pragma unroll
        for (int off = 16; off; off >>= 1)
            lmax = fmaxf(lmax, __shfl_xor_sync(0xffffffffu, lmax, off));

        float lsum = 0.f;
        for (int t = lane; t <= s; t += 32) {
            float p = expf(mysc[t] - lmax);
            mysc[t] = p;
            lsum += p;
        }
        #pragma unroll
        for (int off = 16; off; off >>= 1)
            lsum += __shfl_xor_sync(0xffffffffu, lsum, off);
        float inv = 1.f / lsum;
        __syncwarp();

        float acc0 = 0.f, acc1 = 0.f;
        for (int t = 0; t <= s; t++) {
            float p = mysc[t];
            acc0 += p * vs[t*KSTR + lane];
            acc1 += p * vs[t*KSTR + lane + 32];
        }
        float* orow = o + (size_t)(b*SEQ + s)*DIM + h*64;
        orow[lane]      = acc0 * inv;
        orow[lane + 32] = acc1 * inv;
        __syncwarp();
    }
}

// ---------------- residual add + LayerNorm ----------------
__global__ void add_ln_kernel(const float* __restrict__ x, const float* __restrict__ r,
                              const float* __restrict__ sc, const float* __restrict__ bi,
                              float* __restrict__ out)
{
    __shared__ float buf[DIM];
    __shared__ float red1[8], red2[8];
    int row = blockIdx.x, tid = threadIdx.x, lane = tid & 31, w = tid >> 5;
    const float* xr = x + (size_t)row*DIM;
    const float* rr = r + (size_t)row*DIM;

    float s = 0.f;
    for (int i = tid; i < DIM; i += 256) { float v = xr[i] + rr[i]; buf[i] = v; s += v; }
    #pragma unroll
    for (int off = 16; off; off >>= 1) s += __shfl_xor_sync(0xffffffffu, s, off);
    if (lane == 0) red1[w] = s;
    __syncthreads();
    float tot = 0.f;
    #pragma unroll
    for (int i = 0; i < 8; i++) tot += red1[i];
    float mu = tot * (1.f / DIM);

    float vsum = 0.f;
    for (int i = tid; i < DIM; i += 256) { float d = buf[i] - mu; vsum += d*d; }
    #pragma unroll
    for (int off = 16; off; off >>= 1) vsum += __shfl_xor_sync(0xffffffffu, vsum, off);
    if (lane == 0) red2[w] = vsum;
    __syncthreads();
    float vtot = 0.f;
    #pragma unroll
    for (int i = 0; i < 8; i++) vtot += red2[i];
    float inv = rsqrtf(vtot * (1.f / DIM) + 1e-5f);

    float* orow = out + (size_t)row*DIM;
    for (int i = tid; i < DIM; i += 256)
        orow[i] = (buf[i] - mu) * inv * sc[i] + bi[i];
}

// ---------------- softmax: padded logits -> d_out ----------------
__global__ void softmax_rows(const float* __restrict__ in, float* __restrict__ out)
{
    int row = blockIdx.x, tid = threadIdx.x, lane = tid & 31, w = tid >> 5;
    const float* p = in + (size_t)row * NPADV;
    float* q = out + (size_t)row * VOC;
    __shared__ float smm[8], sss[8];

    float m = -INFINITY, s = 0.f;
    for (int i = tid; i < VOC; i += 256) {
        float xv = p[i];
        if (xv > m) { s = s * expf(m - xv) + 1.f; m = xv; }
        else        { s += expf(xv - m); }
    }
    #pragma unroll
    for (int off = 16; off; off >>= 1) {
        float m2 = __shfl_xor_sync(0xffffffffu, m, off);
        float s2 = __shfl_xor_sync(0xffffffffu, s, off);
        float mn = fmaxf(m, m2);
        s = s * expf(m - mn) + s2 * expf(m2 - mn);
        m = mn;
    }
    if (lane == 0) { smm[w] = m; sss[w] = s; }
    __syncthreads();
    if (tid == 0) {
        float M = smm[0], Sv = sss[0];
        #pragma unroll
        for (int i = 1; i < 8; i++) {
            float m2 = smm[i], s2 = sss[i];
            float mn = fmaxf(M, m2);
            Sv = Sv * expf(M - mn) + s2 * expf(m2 - mn);
            M = mn;
        }
        smm[0] = M; sss[0] = 1.f / Sv;
    }
    __syncthreads();
    float M = smm[0], inv = sss[0];
    for (int i = tid; i < VOC; i += 256)
        q[i] = expf(p[i] - M) * inv;
}

// ---------------- host driver ----------------
extern "C" void kernel_launch(void* const* d_in, const int* in_sizes, int n_in,
                              void* d_out, int out_size)
{
    const float* img   = (const float*)d_in[0];
    const int*   tok   = (const int*)  d_in[1];
    const int*   tmask = (const int*)  d_in[2];
    const float* temb  = (const float*)d_in[3];
    const float* sep   = (const float*)d_in[4];
    const float* Wq    = (const float*)d_in[5];
    const float* bq    = (const float*)d_in[6];
    const float* Wk    = (const float*)d_in[7];
    const float* bk    = (const float*)d_in[8];
    const float* Wv    = (const float*)d_in[9];
    const float* bv    = (const float*)d_in[10];
    const float* ln1s  = (const float*)d_in[11];
    const float* ln1b  = (const float*)d_in[12];
    const float* W1    = (const float*)d_in[13];
    const float* b1    = (const float*)d_in[14];
    const float* W2    = (const float*)d_in[15];
    const float* b2    = (const float*)d_in[16];
    const float* ln2s  = (const float*)d_in[17];
    const float* ln2b  = (const float*)d_in[18];
    const float* Wout  = (const float*)d_in[19];
    const float* bout  = (const float*)d_in[20];
    float* out = (float*)d_out;

    float *px, *pqkv, *po, *pff, *pt, *pb, *plog;
    __nv_bfloat16 *pah, *pal, *pbh, *pbl;
    cudaGetSymbolAddress((void**)&px,   g_x);
    cudaGetSymbolAddress((void**)&pqkv, g_qkv);
    cudaGetSymbolAddress((void**)&po,   g_o);
    cudaGetSymbolAddress((void**)&pff,  g_ff);
    cudaGetSymbolAddress((void**)&pt,   g_t);
    cudaGetSymbolAddress((void**)&pb,   g_b);
    cudaGetSymbolAddress((void**)&plog, g_logits);
    cudaGetSymbolAddress((void**)&pah,  g_ah);
    cudaGetSymbolAddress((void**)&pal,  g_al);
    cudaGetSymbolAddress((void**)&pbh,  g_bth);
    cudaGetSymbolAddress((void**)&pbl,  g_btl);

    const int ATTN_SMEM = (SEQ*KSTR*2 + 8*64 + 8*224) * 4 + 256;
    cudaFuncSetAttribute(attn_kernel, cudaFuncAttributeMaxDynamicSharedMemorySize, ATTN_SMEM);
    cudaFuncSetAttribute(gemm_mma<8,3,1>, cudaFuncAttributeMaxDynamicSharedMemorySize, DSMEM8);
    cudaFuncSetAttribute(gemm_mma<4,2,2>, cudaFuncAttributeMaxDynamicSharedMemorySize, DSMEM4);

    embed_kernel<<<MROWS, 256>>>(img, tok, temb, sep, px);

    #define ACONV(src, K)  a_convert<<<(int)(((size_t)MPAD*(K) + 255)/256), 256>>>(src, MROWS, K)
    #define GEMM8(bias, C, K, ldc, Nreal, Npad, relu) \
        gemm_mma<8,3,1><<<dim3(MPAD/128, (Npad)/256), 256, DSMEM8>>>(pah, pal, pbh, pbl, bias, C, K, ldc, Nreal, MROWS, relu)
    #define GEMM4(bias, C, K, ldc, Nreal, Npad, relu) \
        gemm_mma<4,2,2><<<dim3(MPAD/128, (Npad)/128), 256, DSMEM4>>>(pah, pal, pbh, pbl, bias, C, K, ldc, Nreal, MROWS, relu)

    for (int l = 0; l < NL; l++) {
        const size_t woff = (size_t)l * NH * DIM * HD;
        // QKV
        qkvw_convert<<<(QKVW*DIM + 255)/256, 256>>>(Wq + woff, Wk + woff, Wv + woff,
                                                    bq + (size_t)l*DIM, bk + (size_t)l*DIM,
                                                    bv + (size_t)l*DIM);
        ACONV(px, DIM);
        GEMM8(pb, pqkv, DIM, QKVW, QKVW, QKVW, 0);
        attn_kernel<<<BATCH*NH*4, 256, ATTN_SMEM>>>(pqkv, tmask, po);
        add_ln_kernel<<<MROWS, 256>>>(px, po, ln1s + (size_t)l*DIM, ln1b + (size_t)l*DIM, px);
        // FFN1
        ACONV(px, DIM);
        wt_convert<<<dim3(FF/32, DIM/32), dim3(32, 8)>>>(W1 + (size_t)l*DIM*FF, DIM, FF);
        GEMM8(b1 + (size_t)l*FF, pff, DIM, FF, FF, FF, 1);
        // FFN2 (N=768 -> 128-wide tiles, 2 CTA/SM)
        ACONV(pff, FF);
        wt_convert<<<dim3(DIM/32, FF/32), dim3(32, 8)>>>(W2 + (size_t)l*FF*DIM, FF, DIM);
        GEMM4(b2 + (size_t)l*DIM, pt, FF, DIM, DIM, DIM, 0);
        add_ln_kernel<<<MROWS, 256>>>(px, pt, ln2s + (size_t)l*DIM, ln2b + (size_t)l*DIM, px);
    }

    // vocab projection (padded logits) + softmax into d_out
    ACONV(px, DIM);
    wt_convert<<<dim3(NPADV/32, DIM/32), dim3(32, 8)>>>(Wout, DIM, VOC);
    GEMM8(bout, plog, DIM, NPADV, VOC, NPADV, 0);
    softmax_rows<<<MROWS, 256>>>(plog, out);
}

// round 7
// speedup vs baseline: 1.1048x; 1.1048x over previous
#include <cuda_runtime.h>
#include <cuda_bf16.h>
#include <math.h>
#include <stdint.h>

// ---------------- problem constants ----------------
#define BATCH 16
#define IMG   197
#define TXT   24
#define SEQ   222
#define DIM   768
#define NH    12
#define HD    64
#define NL    6
#define VOC   50257
#define FF    3072
#define MROWS (BATCH*SEQ)  // 3552
#define QKVW  (3*DIM)      // 2304
#define MPAD  3584         // 28 * 128
#define NPADV 50432        // 394 * 128
#define KMAX  3072

// ---------------- GEMM tiling (mma.sync + ldmatrix, R5 config + 1-barrier pipeline) ----
#define TKC   32                 // K per stage
#define ASTR  40                 // smem row stride in bf16 (80B -> conflict-free LDSM)
#define MATSZ (128*ASTR*2)       // 10240 B per matrix tile
#define STAGESZ (4*MATSZ)        // Ah,Al,Bh,Bl = 40960 B
#define DSMEM (2*STAGESZ)        // 81920 B  (x2 CTAs = 160KB < 228KB)
#define MIOFF (16*ASTR*2)        // 1280 B: 16 rows

// ---------------- device scratch ----------------
__device__ float g_x   [MROWS*DIM];
__device__ float g_qkv [MROWS*QKVW];
__device__ float g_o   [MROWS*DIM];
__device__ float g_ff  [MROWS*FF];
__device__ float g_t   [MROWS*DIM];
__device__ float g_b   [QKVW];
__device__ __nv_bfloat16 g_ah [MPAD*KMAX];
__device__ __nv_bfloat16 g_al [MPAD*KMAX];
__device__ __nv_bfloat16 g_bth[(size_t)NPADV*DIM];
__device__ __nv_bfloat16 g_btl[(size_t)NPADV*DIM];
__device__ float g_logits[(size_t)MROWS*NPADV];

// ---------------- PTX helpers ----------------
__device__ __forceinline__ uint32_t s2u(const void* p) {
    uint32_t a;
    asm("{ .reg .u64 t; cvta.to.shared.u64 t, %1; cvt.u32.u64 %0, t; }" : "=r"(a) : "l"(p));
    return a;
}
#define CP16(dst, src)   asm volatile("cp.async.cg.shared.global [%0], [%1], 16;" :: "r"(dst), "l"(src))
#define CP_COMMIT()      asm volatile("cp.async.commit_group;" ::: "memory")
#define CP_WAIT(n)       asm volatile("cp.async.wait_group %0;" :: "n"(n) : "memory")

__device__ __forceinline__ void mma16816(float* c, const uint32_t* a, const uint32_t* b) {
    asm volatile(
        "mma.sync.aligned.m16n8k16.row.col.f32.bf16.bf16.f32 "
        "{%0,%1,%2,%3}, {%4,%5,%6,%7}, {%8,%9}, {%0,%1,%2,%3};"
        : "+f"(c[0]), "+f"(c[1]), "+f"(c[2]), "+f"(c[3])
        : "r"(a[0]), "r"(a[1]), "r"(a[2]), "r"(a[3]), "r"(b[0]), "r"(b[1]));
}
__device__ __forceinline__ void ldsm4(uint32_t* r, uint32_t addr) {
    asm volatile("ldmatrix.sync.aligned.m8n8.x4.shared.b16 {%0,%1,%2,%3}, [%4];"
                 : "=r"(r[0]), "=r"(r[1]), "=r"(r[2]), "=r"(r[3]) : "r"(addr));
}

// ---------------- embedding ----------------
__global__ void embed_kernel(const float* __restrict__ img, const int* __restrict__ tok,
                             const float* __restrict__ temb, const float* __restrict__ sep,
                             float* __restrict__ x)
{
    int row = blockIdx.x;
    int b = row / SEQ, s = row % SEQ;
    const float* src;
    if (s < IMG)       src = img + (size_t)(b*IMG + s)*DIM;
    else if (s == IMG) src = sep;
    else               src = temb + (size_t)tok[b*TXT + (s-IMG-1)] * DIM;
    float* dst = x + (size_t)row*DIM;
    for (int i = threadIdx.x; i < DIM; i += blockDim.x) dst[i] = src[i];
}

// ---------------- activation split ----------------
__global__ void a_convert(const float* __restrict__ src, int Ms, int K)
{
    size_t idx = (size_t)blockIdx.x*256 + threadIdx.x;
    if (idx >= (size_t)MPAD*K) return;
    int row = (int)(idx / K);
    float v = (row < Ms) ? src[idx] : 0.f;
    __nv_bfloat16 h = __float2bfloat16(v);
    g_ah[idx] = h;
    g_al[idx] = __float2bfloat16(v - __bfloat162float(h));
}

// ---------------- weight transpose+split ----------------
__global__ void wt_convert(const float* __restrict__ src, int K, int N)
{
    __shared__ float t[32][33];
    int n0 = blockIdx.x*32, k0 = blockIdx.y*32;
    int tx = threadIdx.x, ty = threadIdx.y;
    #pragma unroll
    for (int j = 0; j < 32; j += 8) {
        int n = n0 + tx;
        t[ty+j][tx] = (n < N) ? src[(size_t)(k0+ty+j)*N + n] : 0.f;
    }
    __syncthreads();
    #pragma unroll
    for (int j = 0; j < 32; j += 8) {
        int n = n0 + ty + j, k = k0 + tx;
        float v = t[tx][ty+j];
        __nv_bfloat16 h = __float2bfloat16(v);
        size_t o = (size_t)n*K + k;
        g_bth[o] = h;
        g_btl[o] = __float2bfloat16(v - __bfloat162float(h));
    }
}

// ---------------- QKV weight gather+split ----------------
__global__ void qkvw_convert(const float* __restrict__ Wq, const float* __restrict__ Wk,
                             const float* __restrict__ Wv,
                             const float* __restrict__ bq, const float* __restrict__ bk,
                             const float* __restrict__ bv)
{
    int idx = blockIdx.x*256 + threadIdx.x;
    if (idx < QKVW*DIM) {
        int c = idx / DIM, d = idx % DIM;
        int which = c / DIM, w2 = c % DIM;
        int h = w2 >> 6, e = w2 & 63;
        const float* W = (which == 0) ? Wq : (which == 1) ? Wk : Wv;
        float v = W[(size_t)h*DIM*HD + (size_t)d*HD + e];
        __nv_bfloat16 hh = __float2bfloat16(v);
        g_bth[idx] = hh;
        g_btl[idx] = __float2bfloat16(v - __bfloat162float(hh));
    }
    if (idx < QKVW) {
        int which = idx / DIM, cc = idx % DIM;
        const float* bb = (which == 0) ? bq : (which == 1) ? bk : bv;
        g_b[idx] = bb[cc];
    }
}

// ---------------- mma.sync bf16 3-pass GEMM: C[Mreal,ldc] = A*B^T + bias ----------------
// CTA tile 128x128, 8 warps of 64x32, 2 CTAs/SM, 2-stage cp.async,
// single barrier per K-chunk with loads issued after the barrier (overlap compute).
__global__ __launch_bounds__(256, 2)
void gemm_mma(const __nv_bfloat16* __restrict__ Ah, const __nv_bfloat16* __restrict__ Al,
              const __nv_bfloat16* __restrict__ Bh, const __nv_bfloat16* __restrict__ Bl,
              const float* __restrict__ bias, float* __restrict__ C,
              int K, int ldc, int Nreal, int Mreal, int relu)
{
    extern __shared__ char dsm[];
    const int tid = threadIdx.x;
    const int wid = tid >> 5, lane = tid & 31;
    const int m0 = blockIdx.x * 128, n0 = blockIdx.y * 128;
    const int wm = wid >> 2, wn = wid & 3;
    const int g = lane >> 2, t = lane & 3;
    const int nk = K / TKC;
    const uint32_t sb = s2u(dsm);

    const int lm = lane >> 3, lj = lane & 7;
    const uint32_t aLane = ((uint32_t)((wm*64 + (lm & 1)*8 + lj) * ASTR + ((lm >> 1) * 8))) * 2;
    const uint32_t bLane = ((uint32_t)((wn*32 + (lm >> 1)*8 + lj) * ASTR + ((lm & 1) * 8))) * 2;

    float acc[4][4][4];
    #pragma unroll
    for (int mi = 0; mi < 4; mi++)
        #pragma unroll
        for (int ni = 0; ni < 4; ni++)
            #pragma unroll
            for (int r = 0; r < 4; r++) acc[mi][ni][r] = 0.f;

    #define LOAD_ST(p, kc) do {                                                     \
        int k0_ = (kc) * TKC;                                                       \
        _Pragma("unroll")                                                           \
        for (int c_ = tid; c_ < 2048; c_ += 256) {                                  \
            int mat_ = c_ >> 9, mr_ = c_ & 511;                                     \
            int row_ = mr_ >> 2, c16_ = mr_ & 3;                                    \
            const __nv_bfloat16* sp_ =                                              \
                ((mat_ == 0) ? Ah : (mat_ == 1) ? Al : (mat_ == 2) ? Bh : Bl)       \
                + (size_t)(((mat_ < 2) ? m0 : n0) + row_) * K + k0_ + c16_*8;       \
            uint32_t dst_ = sb + (p)*STAGESZ + mat_*MATSZ + row_*80 + c16_*16;      \
            CP16(dst_, sp_);                                                        \
        }                                                                           \
        CP_COMMIT();                                                                \
    } while (0)

    LOAD_ST(0, 0);

    for (int kc = 0; kc < nk; kc++) {
        int p = kc & 1;
        CP_WAIT(0);          // per-thread: own copies for stage p done
        __syncthreads();     // all threads' copies visible; prev compute done
        if (kc + 1 < nk) LOAD_ST(p ^ 1, kc + 1);   // overlaps compute below

        const uint32_t stg = sb + p*STAGESZ;
        const uint32_t aB = stg + aLane;
        const uint32_t bB = stg + 2*MATSZ + bLane;

        #pragma unroll
        for (int ks = 0; ks < 2; ks++) {
            const uint32_t kof = ks * 32;
            uint32_t af[16], bhf[8], blf[8];
            ldsm4(bhf,     bB + kof);
            ldsm4(bhf + 4, bB + MIOFF + kof);
            ldsm4(blf,     bB + MATSZ + kof);
            ldsm4(blf + 4, bB + MATSZ + MIOFF + kof);
            #pragma unroll
            for (int mi = 0; mi < 4; mi++) ldsm4(af + mi*4, aB + mi*MIOFF + kof);
            #pragma unroll
            for (int mi = 0; mi < 4; mi++)
                #pragma unroll
                for (int ni = 0; ni < 4; ni++)
                    mma16816(acc[mi][ni], af + mi*4, bhf + ni*2);
            #pragma unroll
            for (int mi = 0; mi < 4; mi++)
                #pragma unroll
                for (int ni = 0; ni < 4; ni++)
                    mma16816(acc[mi][ni], af + mi*4, blf + ni*2);
            #pragma unroll
            for (int mi = 0; mi < 4; mi++) ldsm4(af + mi*4, aB + MATSZ + mi*MIOFF + kof);
            #pragma unroll
            for (int mi = 0; mi < 4; mi++)
                #pragma unroll
                for (int ni = 0; ni < 4; ni++)
                    mma16816(acc[mi][ni], af + mi*4, bhf + ni*2);
        }
        // no trailing barrier: next iteration's CP_WAIT + barrier covers reuse
    }

    // epilogue
    #pragma unroll
    for (int mi = 0; mi < 4; mi++) {
        int gm0 = m0 + wm*64 + mi*16 + g;
        #pragma unroll
        for (int ni = 0; ni < 4; ni++) {
            int gn = n0 + wn*32 + ni*8 + t*2;
            float bx = (gn     < Nreal) ? bias[gn]     : 0.f;
            float by = (gn + 1 < Nreal) ? bias[gn + 1] : 0.f;
            float c0 = acc[mi][ni][0] + bx, c1 = acc[mi][ni][1] + by;
            float c2 = acc[mi][ni][2] + bx, c3 = acc[mi][ni][3] + by;
            if (relu) {
                c0 = fmaxf(c0, 0.f); c1 = fmaxf(c1, 0.f);
                c2 = fmaxf(c2, 0.f); c3 = fmaxf(c3, 0.f);
            }
            if (gm0 < Mreal)
                *reinterpret_cast<float2*>(C + (size_t)gm0*ldc + gn) = make_float2(c0, c1);
            if (gm0 + 8 < Mreal)
                *reinterpret_cast<float2*>(C + (size_t)(gm0+8)*ldc + gn) = make_float2(c2, c3);
        }
    }
}

// ---------------- attention: 4-way q split per (b,h) ----------------
#define KSTR 65
__global__ void attn_kernel(const float* __restrict__ qkv,
                            const int* __restrict__ tmask,
                            float* __restrict__ o)
{
    int bh = blockIdx.x >> 2, z = blockIdx.x & 3;
    int b = bh / NH, h = bh % NH;
    extern __shared__ float sm[];
    float* ks = sm;
    float* vs = ks + SEQ*KSTR;
    float* qs = vs + SEQ*KSTR;
    float* sc = qs + 8*64;
    unsigned char* valid = (unsigned char*)(sc + 8*224);

    int tid = threadIdx.x, lane = tid & 31, w = tid >> 5;
    const float* base = qkv + (size_t)b * SEQ * QKVW;

    for (int i = tid; i < SEQ*HD; i += 256) {
        int t = i >> 6, e = i & 63;
        ks[t*KSTR + e] = base[(size_t)t*QKVW +   DIM + h*64 + e];
        vs[t*KSTR + e] = base[(size_t)t*QKVW + 2*DIM + h*64 + e];
    }
    for (int t = tid; t < SEQ; t += 256)
        valid[t] = (t < SEQ - TXT) ? 1 : (tmask[b*TXT + t - (SEQ-TXT)] != 0);
    __syncthreads();

    float* myq  = qs + w*64;
    float* mysc = sc + w*224;
    for (int s = (w << 2) + z; s < SEQ; s += 32) {
        myq[lane]      = base[(size_t)s*QKVW + h*64 + lane];
        myq[lane + 32] = base[(size_t)s*QKVW + h*64 + lane + 32];
        __syncwarp();

        float lmax = -INFINITY;
        for (int t = lane; t <= s; t += 32) {
            float d = -INFINITY;
            if (valid[t]) {
                d = 0.f;
                #pragma unroll
                for (int e = 0; e < 64; e++) d += myq[e] * ks[t*KSTR + e];
                d *= 0.125f;
            }
            mysc[t] = d;
            lmax = fmaxf(lmax, d);
        }
        #pragma unroll
        for (int off = 16; off; off >>= 1)
            lmax = fmaxf(lmax, __shfl_xor_sync(0xffffffffu, lmax, off));

        float lsum = 0.f;
        for (int t = lane; t <= s; t += 32) {
            float p = expf(mysc[t] - lmax);
            mysc[t] = p;
            lsum += p;
        }
        #pragma unroll
        for (int off = 16; off; off >>= 1)
            lsum += __shfl_xor_sync(0xffffffffu, lsum, off);
        float inv = 1.f / lsum;
        __syncwarp();

        float acc0 = 0.f, acc1 = 0.f;
        for (int t = 0; t <= s; t++) {
            float p = mysc[t];
            acc0 += p * vs[t*KSTR + lane];
            acc1 += p * vs[t*KSTR + lane + 32];
        }
        float* orow = o + (size_t)(b*SEQ + s)*DIM + h*64;
        orow[lane]      = acc0 * inv;
        orow[lane + 32] = acc1 * inv;
        __syncwarp();
    }
}

// ---------------- residual add + LayerNorm ----------------
__global__ void add_ln_kernel(const float* __restrict__ x, const float* __restrict__ r,
                              const float* __restrict__ sc, const float* __restrict__ bi,
                              float* __restrict__ out)
{
    __shared__ float buf[DIM];
    __shared__ float red1[8], red2[8];
    int row = blockIdx.x, tid = threadIdx.x, lane = tid & 31, w = tid >> 5;
    const float* xr = x + (size_t)row*DIM;
    const float* rr = r + (size_t)row*DIM;

    float s = 0.f;
    for (int i = tid; i < DIM; i += 256) { float v = xr[i] + rr[i]; buf[i] = v; s += v; }
    #pragma unroll
    for (int off = 16; off; off >>= 1) s += __shfl_xor_sync(0xffffffffu, s, off);
    if (lane == 0) red1[w] = s;
    __syncthreads();
    float tot = 0.f;
    #pragma unroll
    for (int i = 0; i < 8; i++) tot += red1[i];
    float mu = tot * (1.f / DIM);

    float vsum = 0.f;
    for (int i = tid; i < DIM; i += 256) { float d = buf[i] - mu; vsum += d*d; }
    #pragma unroll
    for (int off = 16; off; off >>= 1) vsum += __shfl_xor_sync(0xffffffffu, vsum, off);
    if (lane == 0) red2[w] = vsum;
    __syncthreads();
    float vtot = 0.f;
    #pragma unroll
    for (int i = 0; i < 8; i++) vtot += red2[i];
    float inv = rsqrtf(vtot * (1.f / DIM) + 1e-5f);

    float* orow = out + (size_t)row*DIM;
    for (int i = tid; i < DIM; i += 256)
        orow[i] = (buf[i] - mu) * inv * sc[i] + bi[i];
}

// ---------------- softmax: padded logits -> d_out ----------------
__global__ void softmax_rows(const float* __restrict__ in, float* __restrict__ out)
{
    int row = blockIdx.x, tid = threadIdx.x, lane = tid & 31, w = tid >> 5;
    const float* p = in + (size_t)row * NPADV;
    float* q = out + (size_t)row * VOC;
    __shared__ float smm[8], sss[8];

    float m = -INFINITY, s = 0.f;
    for (int i = tid; i < VOC; i += 256) {
        float xv = p[i];
        if (xv > m) { s = s * expf(m - xv) + 1.f; m = xv; }
        else        { s += expf(xv - m); }
    }
    #pragma unroll
    for (int off = 16; off; off >>= 1) {
        float m2 = __shfl_xor_sync(0xffffffffu, m, off);
        float s2 = __shfl_xor_sync(0xffffffffu, s, off);
        float mn = fmaxf(m, m2);
        s = s * expf(m - mn) + s2 * expf(m2 - mn);
        m = mn;
    }
    if (lane == 0) { smm[w] = m; sss[w] = s; }
    __syncthreads();
    if (tid == 0) {
        float M = smm[0], Sv = sss[0];
        #pragma unroll
        for (int i = 1; i < 8; i++) {
            float m2 = smm[i], s2 = sss[i];
            float mn = fmaxf(M, m2);
            Sv = Sv * expf(M - mn) + s2 * expf(m2 - mn);
            M = mn;
        }
        smm[0] = M; sss[0] = 1.f / Sv;
    }
    __syncthreads();
    float M = smm[0], inv = sss[0];
    for (int i = tid; i < VOC; i += 256)
        q[i] = expf(p[i] - M) * inv;
}

// ---------------- host driver ----------------
extern "C" void kernel_launch(void* const* d_in, const int* in_sizes, int n_in,
                              void* d_out, int out_size)
{
    const float* img   = (const float*)d_in[0];
    const int*   tok   = (const int*)  d_in[1];
    const int*   tmask = (const int*)  d_in[2];
    const float* temb  = (const float*)d_in[3];
    const float* sep   = (const float*)d_in[4];
    const float* Wq    = (const float*)d_in[5];
    const float* bq    = (const float*)d_in[6];
    const float* Wk    = (const float*)d_in[7];
    const float* bk    = (const float*)d_in[8];
    const float* Wv    = (const float*)d_in[9];
    const float* bv    = (const float*)d_in[10];
    const float* ln1s  = (const float*)d_in[11];
    const float* ln1b  = (const float*)d_in[12];
    const float* W1    = (const float*)d_in[13];
    const float* b1    = (const float*)d_in[14];
    const float* W2    = (const float*)d_in[15];
    const float* b2    = (const float*)d_in[16];
    const float* ln2s  = (const float*)d_in[17];
    const float* ln2b  = (const float*)d_in[18];
    const float* Wout  = (const float*)d_in[19];
    const float* bout  = (const float*)d_in[20];
    float* out = (float*)d_out;

    float *px, *pqkv, *po, *pff, *pt, *pb, *plog;
    __nv_bfloat16 *pah, *pal, *pbh, *pbl;
    cudaGetSymbolAddress((void**)&px,   g_x);
    cudaGetSymbolAddress((void**)&pqkv, g_qkv);
    cudaGetSymbolAddress((void**)&po,   g_o);
    cudaGetSymbolAddress((void**)&pff,  g_ff);
    cudaGetSymbolAddress((void**)&pt,   g_t);
    cudaGetSymbolAddress((void**)&pb,   g_b);
    cudaGetSymbolAddress((void**)&plog, g_logits);
    cudaGetSymbolAddress((void**)&pah,  g_ah);
    cudaGetSymbolAddress((void**)&pal,  g_al);
    cudaGetSymbolAddress((void**)&pbh,  g_bth);
    cudaGetSymbolAddress((void**)&pbl,  g_btl);

    const int ATTN_SMEM = (SEQ*KSTR*2 + 8*64 + 8*224) * 4 + 256;
    cudaFuncSetAttribute(attn_kernel, cudaFuncAttributeMaxDynamicSharedMemorySize, ATTN_SMEM);
    cudaFuncSetAttribute(gemm_mma, cudaFuncAttributeMaxDynamicSharedMemorySize, DSMEM);

    embed_kernel<<<MROWS, 256>>>(img, tok, temb, sep, px);

    #define ACONV(src, K)  a_convert<<<(int)(((size_t)MPAD*(K) + 255)/256), 256>>>(src, MROWS, K)
    #define GEMM(bias, C, K, ldc, Nreal, Npad, relu) \
        gemm_mma<<<dim3(MPAD/128, (Npad)/128), 256, DSMEM>>>(pah, pal, pbh, pbl, bias, C, K, ldc, Nreal, MROWS, relu)

    for (int l = 0; l < NL; l++) {
        const size_t woff = (size_t)l * NH * DIM * HD;
        // QKV
        qkvw_convert<<<(QKVW*DIM + 255)/256, 256>>>(Wq + woff, Wk + woff, Wv + woff,
                                                    bq + (size_t)l*DIM, bk + (size_t)l*DIM,
                                                    bv + (size_t)l*DIM);
        ACONV(px, DIM);
        GEMM(pb, pqkv, DIM, QKVW, QKVW, QKVW, 0);
        attn_kernel<<<BATCH*NH*4, 256, ATTN_SMEM>>>(pqkv, tmask, po);
        add_ln_kernel<<<MROWS, 256>>>(px, po, ln1s + (size_t)l*DIM, ln1b + (size_t)l*DIM, px);
        // FFN1
        ACONV(px, DIM);
        wt_convert<<<dim3(FF/32, DIM/32), dim3(32, 8)>>>(W1 + (size_t)l*DIM*FF, DIM, FF);
        GEMM(b1 + (size_t)l*FF, pff, DIM, FF, FF, FF, 1);
        // FFN2
        ACONV(pff, FF);
        wt_convert<<<dim3(DIM/32, FF/32), dim3(32, 8)>>>(W2 + (size_t)l*FF*DIM, FF, DIM);
        GEMM(b2 + (size_t)l*DIM, pt, FF, DIM, DIM, DIM, 0);
        add_ln_kernel<<<MROWS, 256>>>(px, pt, ln2s + (size_t)l*DIM, ln2b + (size_t)l*DIM, px);
    }

    // vocab projection (padded logits) + softmax into d_out
    ACONV(px, DIM);
    wt_convert<<<dim3(NPADV/32, DIM/32), dim3(32, 8)>>>(Wout, DIM, VOC);
    GEMM(bout, plog, DIM, NPADV, VOC, NPADV, 0);
    softmax_rows<<<MROWS, 256>>>(plog, out);
}

// round 8
// speedup vs baseline: 1.2877x; 1.1656x over previous
#include <cuda_runtime.h>
#include <cuda_bf16.h>
#include <math.h>
#include <stdint.h>

// ---------------- problem constants ----------------
#define BATCH 16
#define IMG   197
#define TXT   24
#define SEQ   222
#define DIM   768
#define NH    12
#define HD    64
#define NL    6
#define VOC   50257
#define FF    3072
#define MROWS (BATCH*SEQ)  // 3552
#define QKVW  (3*DIM)      // 2304
#define MPAD  3584         // 28 * 128
#define NPADV 50432        // 394 * 128
#define KMAX  3072

// ---------------- GEMM tiling (tf32 mma.sync, single pass) ----------------
#define TKC    48                 // K per stage (6 k8-steps)
#define ASTRF  52                 // smem row stride in floats -> (20g+t)%32 all distinct
#define MATSZF (128*ASTRF*4)      // 26624 B per matrix tile
#define STSZ   (2*MATSZF)         // A + B = 53248 B
#define DSMEM  (2*STSZ)           // 106496 B (x2 CTAs = 212992 < 228KB)

// ---------------- device scratch ----------------
__device__ float g_x   [MROWS*DIM];
__device__ float g_qkv [MROWS*QKVW];
__device__ float g_o   [MROWS*DIM];
__device__ float g_ff  [MROWS*FF];
__device__ float g_t   [MROWS*DIM];
__device__ float g_b   [QKVW];
__device__ float g_a   [MPAD*KMAX];          // tf32-rounded activations [MPAD,K]
__device__ float g_bt  [(size_t)NPADV*DIM];  // tf32-rounded weights^T [Npad,K]
__device__ float g_logits[(size_t)MROWS*NPADV];

// ---------------- PTX helpers ----------------
__device__ __forceinline__ uint32_t s2u(const void* p) {
    uint32_t a;
    asm("{ .reg .u64 t; cvta.to.shared.u64 t, %1; cvt.u32.u64 %0, t; }" : "=r"(a) : "l"(p));
    return a;
}
#define CP16(dst, src)   asm volatile("cp.async.cg.shared.global [%0], [%1], 16;" :: "r"(dst), "l"(src))
#define CP_COMMIT()      asm volatile("cp.async.commit_group;" ::: "memory")
#define CP_WAIT(n)       asm volatile("cp.async.wait_group %0;" :: "n"(n) : "memory")

__device__ __forceinline__ float tf32r(float v) {
    uint32_t o;
    asm("cvt.rna.tf32.f32 %0, %1;" : "=r"(o) : "f"(v));
    return __uint_as_float(o);
}
__device__ __forceinline__ void mma_tf32(float* c, const uint32_t* a, const uint32_t* b) {
    asm volatile(
        "mma.sync.aligned.m16n8k8.row.col.f32.tf32.tf32.f32 "
        "{%0,%1,%2,%3}, {%4,%5,%6,%7}, {%8,%9}, {%0,%1,%2,%3};"
        : "+f"(c[0]), "+f"(c[1]), "+f"(c[2]), "+f"(c[3])
        : "r"(a[0]), "r"(a[1]), "r"(a[2]), "r"(a[3]), "r"(b[0]), "r"(b[1]));
}

// ---------------- embedding ----------------
__global__ void embed_kernel(const float* __restrict__ img, const int* __restrict__ tok,
                             const float* __restrict__ temb, const float* __restrict__ sep,
                             float* __restrict__ x)
{
    int row = blockIdx.x;
    int b = row / SEQ, s = row % SEQ;
    const float* src;
    if (s < IMG)       src = img + (size_t)(b*IMG + s)*DIM;
    else if (s == IMG) src = sep;
    else               src = temb + (size_t)tok[b*TXT + (s-IMG-1)] * DIM;
    float* dst = x + (size_t)row*DIM;
    for (int i = threadIdx.x; i < DIM; i += blockDim.x) dst[i] = src[i];
}

// ---------------- activation round: fp32 [Ms,K] -> tf32 [MPAD,K] ----------------
__global__ void a_convert(const float* __restrict__ src, int Ms, int K)
{
    size_t idx = (size_t)blockIdx.x*256 + threadIdx.x;
    if (idx >= (size_t)MPAD*K) return;
    int row = (int)(idx / K);
    float v = (row < Ms) ? src[idx] : 0.f;
    g_a[idx] = tf32r(v);
}

// ---------------- weight transpose+round: fp32 [K,N] -> tf32 [Npad,K] ----------------
__global__ void wt_convert(const float* __restrict__ src, int K, int N)
{
    __shared__ float t[32][33];
    int n0 = blockIdx.x*32, k0 = blockIdx.y*32;
    int tx = threadIdx.x, ty = threadIdx.y;
    #pragma unroll
    for (int j = 0; j < 32; j += 8) {
        int n = n0 + tx;
        t[ty+j][tx] = (n < N) ? src[(size_t)(k0+ty+j)*N + n] : 0.f;
    }
    __syncthreads();
    #pragma unroll
    for (int j = 0; j < 32; j += 8) {
        int n = n0 + ty + j, k = k0 + tx;
        g_bt[(size_t)n*K + k] = tf32r(t[tx][ty+j]);
    }
}

// ---------------- QKV weight gather+round: (H,D,HD)x3 -> tf32 [2304,768] -------------
__global__ void qkvw_convert(const float* __restrict__ Wq, const float* __restrict__ Wk,
                             const float* __restrict__ Wv,
                             const float* __restrict__ bq, const float* __restrict__ bk,
                             const float* __restrict__ bv)
{
    int idx = blockIdx.x*256 + threadIdx.x;
    if (idx < QKVW*DIM) {
        int c = idx / DIM, d = idx % DIM;
        int which = c / DIM, w2 = c % DIM;
        int h = w2 >> 6, e = w2 & 63;
        const float* W = (which == 0) ? Wq : (which == 1) ? Wk : Wv;
        g_bt[idx] = tf32r(W[(size_t)h*DIM*HD + (size_t)d*HD + e]);
    }
    if (idx < QKVW) {
        int which = idx / DIM, cc = idx % DIM;
        const float* bb = (which == 0) ? bq : (which == 1) ? bk : bv;
        g_b[idx] = bb[cc];
    }
}

// ---------------- tf32 mma.sync GEMM: C[Mreal,ldc] = A*B^T + bias ----------------
// CTA 128x128, 8 warps of 64x32, 2 CTAs/SM, 2-stage cp.async, single barrier/chunk.
__global__ __launch_bounds__(256, 2)
void gemm_mma(const float* __restrict__ Aa, const float* __restrict__ Bt,
              const float* __restrict__ bias, float* __restrict__ C,
              int K, int ldc, int Nreal, int Mreal, int relu)
{
    extern __shared__ char dsm[];
    float* smf = (float*)dsm;
    const int tid = threadIdx.x;
    const int wid = tid >> 5, lane = tid & 31;
    const int m0 = blockIdx.x * 128, n0 = blockIdx.y * 128;
    const int wm = wid >> 2, wn = wid & 3;
    const int g = lane >> 2, t = lane & 3;
    const int nk = K / TKC;
    const uint32_t sb = s2u(dsm);

    float acc[4][4][4];
    #pragma unroll
    for (int mi = 0; mi < 4; mi++)
        #pragma unroll
        for (int ni = 0; ni < 4; ni++)
            #pragma unroll
            for (int r = 0; r < 4; r++) acc[mi][ni][r] = 0.f;

    // stage loader: A tile 128x48 + B tile 128x48 (fp32), rows padded to 52 floats.
    // 3072 16B-chunks per stage, 12 per thread.
    #define LOAD_ST(p, kc) do {                                                      \
        int k0_ = (kc) * TKC;                                                        \
        _Pragma("unroll")                                                            \
        for (int c_ = tid; c_ < 3072; c_ += 256) {                                   \
            int isB_ = (c_ >= 1536);                                                 \
            int cc_  = isB_ ? c_ - 1536 : c_;                                        \
            int row_ = cc_ / 12, c4_ = cc_ % 12;                                     \
            const float* sp_ = (isB_ ? Bt + (size_t)(n0 + row_) * K                  \
                                     : Aa + (size_t)(m0 + row_) * K) + k0_ + c4_*4;  \
            uint32_t dst_ = sb + (p)*STSZ + (isB_ ? MATSZF : 0) + row_*208 + c4_*16; \
            CP16(dst_, sp_);                                                         \
        }                                                                            \
        CP_COMMIT();                                                                 \
    } while (0)

    LOAD_ST(0, 0);

    const int aR = (wm*64 + g) * ASTRF + t;          // A frag base (word idx, stage-rel)
    const int bR = (wn*32 + g) * ASTRF + t;          // B frag base

    for (int kc = 0; kc < nk; kc++) {
        int p = kc & 1;
        CP_WAIT(0);
        __syncthreads();
        if (kc + 1 < nk) LOAD_ST(p ^ 1, kc + 1);     // overlaps compute below

        const float* sA = smf + (size_t)p * (STSZ/4);
        const float* sB = sA + MATSZF/4;

        #pragma unroll
        for (int ks = 0; ks < 6; ks++) {
            const int kof = ks * 8;
            uint32_t af[16], bf[8];
            #pragma unroll
            for (int mi = 0; mi < 4; mi++) {
                const float* ap = sA + aR + mi*16*ASTRF + kof;
                af[mi*4+0] = *(const uint32_t*)(ap);
                af[mi*4+1] = *(const uint32_t*)(ap + 8*ASTRF);
                af[mi*4+2] = *(const uint32_t*)(ap + 4);
                af[mi*4+3] = *(const uint32_t*)(ap + 8*ASTRF + 4);
            }
            #pragma unroll
            for (int ni = 0; ni < 4; ni++) {
                const float* bp = sB + bR + ni*8*ASTRF + kof;
                bf[ni*2+0] = *(const uint32_t*)(bp);
                bf[ni*2+1] = *(const uint32_t*)(bp + 4);
            }
            #pragma unroll
            for (int mi = 0; mi < 4; mi++)
                #pragma unroll
                for (int ni = 0; ni < 4; ni++)
                    mma_tf32(acc[mi][ni], af + mi*4, bf + ni*2);
        }
    }

    // epilogue
    #pragma unroll
    for (int mi = 0; mi < 4; mi++) {
        int gm0 = m0 + wm*64 + mi*16 + g;
        #pragma unroll
        for (int ni = 0; ni < 4; ni++) {
            int gn = n0 + wn*32 + ni*8 + t*2;
            float bx = (gn     < Nreal) ? bias[gn]     : 0.f;
            float by = (gn + 1 < Nreal) ? bias[gn + 1] : 0.f;
            float c0 = acc[mi][ni][0] + bx, c1 = acc[mi][ni][1] + by;
            float c2 = acc[mi][ni][2] + bx, c3 = acc[mi][ni][3] + by;
            if (relu) {
                c0 = fmaxf(c0, 0.f); c1 = fmaxf(c1, 0.f);
                c2 = fmaxf(c2, 0.f); c3 = fmaxf(c3, 0.f);
            }
            if (gm0 < Mreal)
                *reinterpret_cast<float2*>(C + (size_t)gm0*ldc + gn) = make_float2(c0, c1);
            if (gm0 + 8 < Mreal)
                *reinterpret_cast<float2*>(C + (size_t)(gm0+8)*ldc + gn) = make_float2(c2, c3);
        }
    }
}

// ---------------- attention: 4-way q split per (b,h) ----------------
#define KSTR 65
__global__ void attn_kernel(const float* __restrict__ qkv,
                            const int* __restrict__ tmask,
                            float* __restrict__ o)
{
    int bh = blockIdx.x >> 2, z = blockIdx.x & 3;
    int b = bh / NH, h = bh % NH;
    extern __shared__ float sm[];
    float* ks = sm;
    float* vs = ks + SEQ*KSTR;
    float* qs = vs + SEQ*KSTR;
    float* sc = qs + 8*64;
    unsigned char* valid = (unsigned char*)(sc + 8*224);

    int tid = threadIdx.x, lane = tid & 31, w = tid >> 5;
    const float* base = qkv + (size_t)b * SEQ * QKVW;

    for (int i = tid; i < SEQ*HD; i += 256) {
        int t = i >> 6, e = i & 63;
        ks[t*KSTR + e] = base[(size_t)t*QKVW +   DIM + h*64 + e];
        vs[t*KSTR + e] = base[(size_t)t*QKVW + 2*DIM + h*64 + e];
    }
    for (int t = tid; t < SEQ; t += 256)
        valid[t] = (t < SEQ - TXT) ? 1 : (tmask[b*TXT + t - (SEQ-TXT)] != 0);
    __syncthreads();

    float* myq  = qs + w*64;
    float* mysc = sc + w*224;
    for (int s = (w << 2) + z; s < SEQ; s += 32) {
        myq[lane]      = base[(size_t)s*QKVW + h*64 + lane];
        myq[lane + 32] = base[(size_t)s*QKVW + h*64 + lane + 32];
        __syncwarp();

        float lmax = -INFINITY;
        for (int t = lane; t <= s; t += 32) {
            float d = -INFINITY;
            if (valid[t]) {
                d = 0.f;
                #pragma unroll
                for (int e = 0; e < 64; e++) d += myq[e] * ks[t*KSTR + e];
                d *= 0.125f;
            }
            mysc[t] = d;
            lmax = fmaxf(lmax, d);
        }
        #pragma unroll
        for (int off = 16; off; off >>= 1)
            lmax = fmaxf(lmax, __shfl_xor_sync(0xffffffffu, lmax, off));

        float lsum = 0.f;
        for (int t = lane; t <= s; t += 32) {
            float p = expf(mysc[t] - lmax);
            mysc[t] = p;
            lsum += p;
        }
        #pragma unroll
        for (int off = 16; off; off >>= 1)
            lsum += __shfl_xor_sync(0xffffffffu, lsum, off);
        float inv = 1.f / lsum;
        __syncwarp();

        float acc0 = 0.f, acc1 = 0.f;
        for (int t = 0; t <= s; t++) {
            float p = mysc[t];
            acc0 += p * vs[t*KSTR + lane];
            acc1 += p * vs[t*KSTR + lane + 32];
        }
        float* orow = o + (size_t)(b*SEQ + s)*DIM + h*64;
        orow[lane]      = acc0 * inv;
        orow[lane + 32] = acc1 * inv;
        __syncwarp();
    }
}

// ---------------- residual add + LayerNorm ----------------
__global__ void add_ln_kernel(const float* __restrict__ x, const float* __restrict__ r,
                              const float* __restrict__ sc, const float* __restrict__ bi,
                              float* __restrict__ out)
{
    __shared__ float buf[DIM];
    __shared__ float red1[8], red2[8];
    int row = blockIdx.x, tid = threadIdx.x, lane = tid & 31, w = tid >> 5;
    const float* xr = x + (size_t)row*DIM;
    const float* rr = r + (size_t)row*DIM;

    float s = 0.f;
    for (int i = tid; i < DIM; i += 256) { float v = xr[i] + rr[i]; buf[i] = v; s += v; }
    #pragma unroll
    for (int off = 16; off; off >>= 1) s += __shfl_xor_sync(0xffffffffu, s, off);
    if (lane == 0) red1[w] = s;
    __syncthreads();
    float tot = 0.f;
    #pragma unroll
    for (int i = 0; i < 8; i++) tot += red1[i];
    float mu = tot * (1.f / DIM);

    float vsum = 0.f;
    for (int i = tid; i < DIM; i += 256) { float d = buf[i] - mu; vsum += d*d; }
    #pragma unroll
    for (int off = 16; off; off >>= 1) vsum += __shfl_xor_sync(0xffffffffu, vsum, off);
    if (lane == 0) red2[w] = vsum;
    __syncthreads();
    float vtot = 0.f;
    #pragma unroll
    for (int i = 0; i < 8; i++) vtot += red2[i];
    float inv = rsqrtf(vtot * (1.f / DIM) + 1e-5f);

    float* orow = out + (size_t)row*DIM;
    for (int i = tid; i < DIM; i += 256)
        orow[i] = (buf[i] - mu) * inv * sc[i] + bi[i];
}

// ---------------- softmax: padded logits -> d_out ----------------
__global__ void softmax_rows(const float* __restrict__ in, float* __restrict__ out)
{
    int row = blockIdx.x, tid = threadIdx.x, lane = tid & 31, w = tid >> 5;
    const float* p = in + (size_t)row * NPADV;
    float* q = out + (size_t)row * VOC;
    __shared__ float smm[8], sss[8];

    float m = -INFINITY, s = 0.f;
    for (int i = tid; i < VOC; i += 256) {
        float xv = p[i];
        if (xv > m) { s = s * expf(m - xv) + 1.f; m = xv; }
        else        { s += expf(xv - m); }
    }
    #pragma unroll
    for (int off = 16; off; off >>= 1) {
        float m2 = __shfl_xor_sync(0xffffffffu, m, off);
        float s2 = __shfl_xor_sync(0xffffffffu, s, off);
        float mn = fmaxf(m, m2);
        s = s * expf(m - mn) + s2 * expf(m2 - mn);
        m = mn;
    }
    if (lane == 0) { smm[w] = m; sss[w] = s; }
    __syncthreads();
    if (tid == 0) {
        float M = smm[0], Sv = sss[0];
        #pragma unroll
        for (int i = 1; i < 8; i++) {
            float m2 = smm[i], s2 = sss[i];
            float mn = fmaxf(M, m2);
            Sv = Sv * expf(M - mn) + s2 * expf(m2 - mn);
            M = mn;
        }
        smm[0] = M; sss[0] = 1.f / Sv;
    }
    __syncthreads();
    float M = smm[0], inv = sss[0];
    for (int i = tid; i < VOC; i += 256)
        q[i] = expf(p[i] - M) * inv;
}

// ---------------- host driver ----------------
extern "C" void kernel_launch(void* const* d_in, const int* in_sizes, int n_in,
                              void* d_out, int out_size)
{
    const float* img   = (const float*)d_in[0];
    const int*   tok   = (const int*)  d_in[1];
    const int*   tmask = (const int*)  d_in[2];
    const float* temb  = (const float*)d_in[3];
    const float* sep   = (const float*)d_in[4];
    const float* Wq    = (const float*)d_in[5];
    const float* bq    = (const float*)d_in[6];
    const float* Wk    = (const float*)d_in[7];
    const float* bk    = (const float*)d_in[8];
    const float* Wv    = (const float*)d_in[9];
    const float* bv    = (const float*)d_in[10];
    const float* ln1s  = (const float*)d_in[11];
    const float* ln1b  = (const float*)d_in[12];
    const float* W1    = (const float*)d_in[13];
    const float* b1    = (const float*)d_in[14];
    const float* W2    = (const float*)d_in[15];
    const float* b2    = (const float*)d_in[16];
    const float* ln2s  = (const float*)d_in[17];
    const float* ln2b  = (const float*)d_in[18];
    const float* Wout  = (const float*)d_in[19];
    const float* bout  = (const float*)d_in[20];
    float* out = (float*)d_out;

    float *px, *pqkv, *po, *pff, *pt, *pb, *plog, *pa, *pbt;
    cudaGetSymbolAddress((void**)&px,   g_x);
    cudaGetSymbolAddress((void**)&pqkv, g_qkv);
    cudaGetSymbolAddress((void**)&po,   g_o);
    cudaGetSymbolAddress((void**)&pff,  g_ff);
    cudaGetSymbolAddress((void**)&pt,   g_t);
    cudaGetSymbolAddress((void**)&pb,   g_b);
    cudaGetSymbolAddress((void**)&plog, g_logits);
    cudaGetSymbolAddress((void**)&pa,   g_a);
    cudaGetSymbolAddress((void**)&pbt,  g_bt);

    const int ATTN_SMEM = (SEQ*KSTR*2 + 8*64 + 8*224) * 4 + 256;
    cudaFuncSetAttribute(attn_kernel, cudaFuncAttributeMaxDynamicSharedMemorySize, ATTN_SMEM);
    cudaFuncSetAttribute(gemm_mma, cudaFuncAttributeMaxDynamicSharedMemorySize, DSMEM);

    embed_kernel<<<MROWS, 256>>>(img, tok, temb, sep, px);

    #define ACONV(src, K)  a_convert<<<(int)(((size_t)MPAD*(K) + 255)/256), 256>>>(src, MROWS, K)
    #define GEMM(bias, C, K, ldc, Nreal, Npad, relu) \
        gemm_mma<<<dim3(MPAD/128, (Npad)/128), 256, DSMEM>>>(pa, pbt, bias, C, K, ldc, Nreal, MROWS, relu)

    for (int l = 0; l < NL; l++) {
        const size_t woff = (size_t)l * NH * DIM * HD;
        // QKV
        qkvw_convert<<<(QKVW*DIM + 255)/256, 256>>>(Wq + woff, Wk + woff, Wv + woff,
                                                    bq + (size_t)l*DIM, bk + (size_t)l*DIM,
                                                    bv + (size_t)l*DIM);
        ACONV(px, DIM);
        GEMM(pb, pqkv, DIM, QKVW, QKVW, QKVW, 0);
        attn_kernel<<<BATCH*NH*4, 256, ATTN_SMEM>>>(pqkv, tmask, po);
        add_ln_kernel<<<MROWS, 256>>>(px, po, ln1s + (size_t)l*DIM, ln1b + (size_t)l*DIM, px);
        // FFN1
        ACONV(px, DIM);
        wt_convert<<<dim3(FF/32, DIM/32), dim3(32, 8)>>>(W1 + (size_t)l*DIM*FF, DIM, FF);
        GEMM(b1 + (size_t)l*FF, pff, DIM, FF, FF, FF, 1);
        // FFN2
        ACONV(pff, FF);
        wt_convert<<<dim3(DIM/32, FF/32), dim3(32, 8)>>>(W2 + (size_t)l*FF*DIM, FF, DIM);
        GEMM(b2 + (size_t)l*DIM, pt, FF, DIM, DIM, DIM, 0);
        add_ln_kernel<<<MROWS, 256>>>(px, pt, ln2s + (size_t)l*DIM, ln2b + (size_t)l*DIM, px);
    }

    // vocab projection (padded logits) + softmax into d_out
    ACONV(px, DIM);
    wt_convert<<<dim3(NPADV/32, DIM/32), dim3(32, 8)>>>(Wout, DIM, VOC);
    GEMM(bout, plog, DIM, NPADV, VOC, NPADV, 0);
    softmax_rows<<<MROWS, 256>>>(plog, out);
}

// round 9
// speedup vs baseline: 1.3859x; 1.0762x over previous
#include <cuda_runtime.h>
#include <cuda_bf16.h>
#include <math.h>
#include <stdint.h>

// ---------------- problem constants ----------------
#define BATCH 16
#define IMG   197
#define TXT   24
#define SEQ   222
#define DIM   768
#define NH    12
#define HD    64
#define NL    6
#define VOC   50257
#define FF    3072
#define MROWS (BATCH*SEQ)  // 3552
#define QKVW  (3*DIM)      // 2304
#define MPAD  3584         // 28 * 128
#define NPADV 50432        // 394 * 128
#define KMAX  3072

// ---------------- GEMM tiling (tf32 mma.sync + ldmatrix) ----------------
#define TKC    48                 // K per stage (6 k8-steps)
#define ASTRF  52                 // smem row stride in floats -> ldmatrix phases tile all banks
#define MATSZF (128*ASTRF*4)      // 26624 B per matrix tile
#define STSZ   (2*MATSZF)         // A + B = 53248 B
#define DSMEM  (2*STSZ)           // 106496 B (x2 CTAs = 212992 < 228KB)

// ---------------- device scratch ----------------
__device__ float g_x   [MROWS*DIM];
__device__ float g_qkv [MROWS*QKVW];
__device__ float g_o   [MROWS*DIM];
__device__ float g_ff  [MROWS*FF];
__device__ float g_t   [MROWS*DIM];
__device__ float g_b   [QKVW];
__device__ float g_a   [MPAD*KMAX];          // tf32-rounded activations [MPAD,K]
__device__ float g_bt  [(size_t)NPADV*DIM];  // tf32-rounded weights^T [Npad,K]
__device__ float g_logits[(size_t)MROWS*NPADV];

// ---------------- PTX helpers ----------------
__device__ __forceinline__ uint32_t s2u(const void* p) {
    uint32_t a;
    asm("{ .reg .u64 t; cvta.to.shared.u64 t, %1; cvt.u32.u64 %0, t; }" : "=r"(a) : "l"(p));
    return a;
}
#define CP16(dst, src)   asm volatile("cp.async.cg.shared.global [%0], [%1], 16;" :: "r"(dst), "l"(src))
#define CP_COMMIT()      asm volatile("cp.async.commit_group;" ::: "memory")
#define CP_WAIT(n)       asm volatile("cp.async.wait_group %0;" :: "n"(n) : "memory")

__device__ __forceinline__ float tf32r(float v) {
    uint32_t o;
    asm("cvt.rna.tf32.f32 %0, %1;" : "=r"(o) : "f"(v));
    return __uint_as_float(o);
}
__device__ __forceinline__ void mma_tf32(float* c, const uint32_t* a, const uint32_t* b) {
    asm volatile(
        "mma.sync.aligned.m16n8k8.row.col.f32.tf32.tf32.f32 "
        "{%0,%1,%2,%3}, {%4,%5,%6,%7}, {%8,%9}, {%0,%1,%2,%3};"
        : "+f"(c[0]), "+f"(c[1]), "+f"(c[2]), "+f"(c[3])
        : "r"(a[0]), "r"(a[1]), "r"(a[2]), "r"(a[3]), "r"(b[0]), "r"(b[1]));
}
__device__ __forceinline__ void ldsm4(uint32_t* r, uint32_t addr) {
    asm volatile("ldmatrix.sync.aligned.m8n8.x4.shared.b16 {%0,%1,%2,%3}, [%4];"
                 : "=r"(r[0]), "=r"(r[1]), "=r"(r[2]), "=r"(r[3]) : "r"(addr));
}

// ---------------- embedding ----------------
__global__ void embed_kernel(const float* __restrict__ img, const int* __restrict__ tok,
                             const float* __restrict__ temb, const float* __restrict__ sep,
                             float* __restrict__ x)
{
    int row = blockIdx.x;
    int b = row / SEQ, s = row % SEQ;
    const float* src;
    if (s < IMG)       src = img + (size_t)(b*IMG + s)*DIM;
    else if (s == IMG) src = sep;
    else               src = temb + (size_t)tok[b*TXT + (s-IMG-1)] * DIM;
    float* dst = x + (size_t)row*DIM;
    for (int i = threadIdx.x; i < DIM; i += blockDim.x) dst[i] = src[i];
}

// ---------------- activation round ----------------
__global__ void a_convert(const float* __restrict__ src, int Ms, int K)
{
    size_t idx = (size_t)blockIdx.x*256 + threadIdx.x;
    if (idx >= (size_t)MPAD*K) return;
    int row = (int)(idx / K);
    float v = (row < Ms) ? src[idx] : 0.f;
    g_a[idx] = tf32r(v);
}

// ---------------- weight transpose+round ----------------
__global__ void wt_convert(const float* __restrict__ src, int K, int N)
{
    __shared__ float t[32][33];
    int n0 = blockIdx.x*32, k0 = blockIdx.y*32;
    int tx = threadIdx.x, ty = threadIdx.y;
    #pragma unroll
    for (int j = 0; j < 32; j += 8) {
        int n = n0 + tx;
        t[ty+j][tx] = (n < N) ? src[(size_t)(k0+ty+j)*N + n] : 0.f;
    }
    __syncthreads();
    #pragma unroll
    for (int j = 0; j < 32; j += 8) {
        int n = n0 + ty + j, k = k0 + tx;
        g_bt[(size_t)n*K + k] = tf32r(t[tx][ty+j]);
    }
}

// ---------------- QKV weight gather+round ----------------
__global__ void qkvw_convert(const float* __restrict__ Wq, const float* __restrict__ Wk,
                             const float* __restrict__ Wv,
                             const float* __restrict__ bq, const float* __restrict__ bk,
                             const float* __restrict__ bv)
{
    int idx = blockIdx.x*256 + threadIdx.x;
    if (idx < QKVW*DIM) {
        int c = idx / DIM, d = idx % DIM;
        int which = c / DIM, w2 = c % DIM;
        int h = w2 >> 6, e = w2 & 63;
        const float* W = (which == 0) ? Wq : (which == 1) ? Wk : Wv;
        g_bt[idx] = tf32r(W[(size_t)h*DIM*HD + (size_t)d*HD + e]);
    }
    if (idx < QKVW) {
        int which = idx / DIM, cc = idx % DIM;
        const float* bb = (which == 0) ? bq : (which == 1) ? bk : bv;
        g_b[idx] = bb[cc];
    }
}

// ---------------- tf32 mma.sync GEMM with ldmatrix frags ----------------
// CTA 128x128, 8 warps of 64x32, 2 CTAs/SM, 2-stage cp.async, single barrier/chunk.
__global__ __launch_bounds__(256, 2)
void gemm_mma(const float* __restrict__ Aa, const float* __restrict__ Bt,
              const float* __restrict__ bias, float* __restrict__ C,
              int K, int ldc, int Nreal, int Mreal, int relu)
{
    extern __shared__ char dsm[];
    const int tid = threadIdx.x;
    const int wid = tid >> 5, lane = tid & 31;
    const int m0 = blockIdx.x * 128, n0 = blockIdx.y * 128;
    const int wm = wid >> 2, wn = wid & 3;
    const int g = lane >> 2, t = lane & 3;
    const int nk = K / TKC;
    const uint32_t sb = s2u(dsm);

    // ldmatrix lane addressing (tf32-as-b16 trick):
    // A x4: matrices {rows g, rows g+8} x {k lo4, k hi4}
    const uint32_t aLaneOff =
        (uint32_t)(((wm*64 + ((lane & 8) ? 8 : 0) + (lane & 7)) * ASTRF)
                   + ((lane & 16) ? 4 : 0)) * 4;
    // B x4: matrices {n-pair lo8, n-pair hi8} x {k lo4, k hi4} (per 16-wide n pair)
    const uint32_t bLaneOff =
        (uint32_t)(((wn*32 + ((lane & 16) ? 8 : 0) + (lane & 7)) * ASTRF)
                   + ((lane & 8) ? 4 : 0)) * 4;

    float acc[4][4][4];
    #pragma unroll
    for (int mi = 0; mi < 4; mi++)
        #pragma unroll
        for (int ni = 0; ni < 4; ni++)
            #pragma unroll
            for (int r = 0; r < 4; r++) acc[mi][ni][r] = 0.f;

    #define LOAD_ST(p, kc) do {                                                      \
        int k0_ = (kc) * TKC;                                                        \
        _Pragma("unroll")                                                            \
        for (int c_ = tid; c_ < 3072; c_ += 256) {                                   \
            int isB_ = (c_ >= 1536);                                                 \
            int cc_  = isB_ ? c_ - 1536 : c_;                                        \
            int row_ = cc_ / 12, c4_ = cc_ % 12;                                     \
            const float* sp_ = (isB_ ? Bt + (size_t)(n0 + row_) * K                  \
                                     : Aa + (size_t)(m0 + row_) * K) + k0_ + c4_*4;  \
            uint32_t dst_ = sb + (p)*STSZ + (isB_ ? MATSZF : 0) + row_*208 + c4_*16; \
            CP16(dst_, sp_);                                                         \
        }                                                                            \
        CP_COMMIT();                                                                 \
    } while (0)

    LOAD_ST(0, 0);

    for (int kc = 0; kc < nk; kc++) {
        int p = kc & 1;
        CP_WAIT(0);
        __syncthreads();
        if (kc + 1 < nk) LOAD_ST(p ^ 1, kc + 1);     // overlaps compute below

        const uint32_t stg = sb + p*STSZ;
        const uint32_t aB = stg + aLaneOff;
        const uint32_t bB = stg + MATSZF + bLaneOff;

        #pragma unroll
        for (int ks = 0; ks < 6; ks++) {
            const uint32_t kof = ks * 32;           // ks*8 words * 4B
            uint32_t af[16], bf[16];
            #pragma unroll
            for (int mi = 0; mi < 4; mi++)
                ldsm4(af + mi*4, aB + mi*(16*ASTRF*4) + kof);
            // B: pair 0 -> bf[0..3] = {n0-7 klo, n0-7 khi, n8-15 klo, n8-15 khi}
            ldsm4(bf,     bB + kof);
            ldsm4(bf + 4, bB + 16*ASTRF*4 + kof);
            #pragma unroll
            for (int mi = 0; mi < 4; mi++) {
                #pragma unroll
                for (int ni = 0; ni < 4; ni++)
                    mma_tf32(acc[mi][ni], af + mi*4, bf + ni*2);
            }
        }
    }

    // epilogue
    #pragma unroll
    for (int mi = 0; mi < 4; mi++) {
        int gm0 = m0 + wm*64 + mi*16 + g;
        #pragma unroll
        for (int ni = 0; ni < 4; ni++) {
            int gn = n0 + wn*32 + ni*8 + t*2;
            float bx = (gn     < Nreal) ? bias[gn]     : 0.f;
            float by = (gn + 1 < Nreal) ? bias[gn + 1] : 0.f;
            float c0 = acc[mi][ni][0] + bx, c1 = acc[mi][ni][1] + by;
            float c2 = acc[mi][ni][2] + bx, c3 = acc[mi][ni][3] + by;
            if (relu) {
                c0 = fmaxf(c0, 0.f); c1 = fmaxf(c1, 0.f);
                c2 = fmaxf(c2, 0.f); c3 = fmaxf(c3, 0.f);
            }
            if (gm0 < Mreal)
                *reinterpret_cast<float2*>(C + (size_t)gm0*ldc + gn) = make_float2(c0, c1);
            if (gm0 + 8 < Mreal)
                *reinterpret_cast<float2*>(C + (size_t)(gm0+8)*ldc + gn) = make_float2(c2, c3);
        }
    }
}

// ---------------- attention: 4-way q split per (b,h) ----------------
#define KSTR 65
__global__ void attn_kernel(const float* __restrict__ qkv,
                            const int* __restrict__ tmask,
                            float* __restrict__ o)
{
    int bh = blockIdx.x >> 2, z = blockIdx.x & 3;
    int b = bh / NH, h = bh % NH;
    extern __shared__ float sm[];
    float* ks = sm;
    float* vs = ks + SEQ*KSTR;
    float* qs = vs + SEQ*KSTR;
    float* sc = qs + 8*64;
    unsigned char* valid = (unsigned char*)(sc + 8*224);

    int tid = threadIdx.x, lane = tid & 31, w = tid >> 5;
    const float* base = qkv + (size_t)b * SEQ * QKVW;

    for (int i = tid; i < SEQ*HD; i += 256) {
        int t = i >> 6, e = i & 63;
        ks[t*KSTR + e] = base[(size_t)t*QKVW +   DIM + h*64 + e];
        vs[t*KSTR + e] = base[(size_t)t*QKVW + 2*DIM + h*64 + e];
    }
    for (int t = tid; t < SEQ; t += 256)
        valid[t] = (t < SEQ - TXT) ? 1 : (tmask[b*TXT + t - (SEQ-TXT)] != 0);
    __syncthreads();

    float* myq  = qs + w*64;
    float* mysc = sc + w*224;
    for (int s = (w << 2) + z; s < SEQ; s += 32) {
        myq[lane]      = base[(size_t)s*QKVW + h*64 + lane];
        myq[lane + 32] = base[(size_t)s*QKVW + h*64 + lane + 32];
        __syncwarp();

        float lmax = -INFINITY;
        for (int t = lane; t <= s; t += 32) {
            float d = -INFINITY;
            if (valid[t]) {
                d = 0.f;
                #pragma unroll
                for (int e = 0; e < 64; e++) d += myq[e] * ks[t*KSTR + e];
                d *= 0.125f;
            }
            mysc[t] = d;
            lmax = fmaxf(lmax, d);
        }
        #pragma unroll
        for (int off = 16; off; off >>= 1)
            lmax = fmaxf(lmax, __shfl_xor_sync(0xffffffffu, lmax, off));

        float lsum = 0.f;
        for (int t = lane; t <= s; t += 32) {
            float p = expf(mysc[t] - lmax);
            mysc[t] = p;
            lsum += p;
        }
        #pragma unroll
        for (int off = 16; off; off >>= 1)
            lsum += __shfl_xor_sync(0xffffffffu, lsum, off);
        float inv = 1.f / lsum;
        __syncwarp();

        float acc0 = 0.f, acc1 = 0.f;
        for (int t = 0; t <= s; t++) {
            float p = mysc[t];
            acc0 += p * vs[t*KSTR + lane];
            acc1 += p * vs[t*KSTR + lane + 32];
        }
        float* orow = o + (size_t)(b*SEQ + s)*DIM + h*64;
        orow[lane]      = acc0 * inv;
        orow[lane + 32] = acc1 * inv;
        __syncwarp();
    }
}

// ---------------- residual add + LayerNorm ----------------
__global__ void add_ln_kernel(const float* __restrict__ x, const float* __restrict__ r,
                              const float* __restrict__ sc, const float* __restrict__ bi,
                              float* __restrict__ out)
{
    __shared__ float buf[DIM];
    __shared__ float red1[8], red2[8];
    int row = blockIdx.x, tid = threadIdx.x, lane = tid & 31, w = tid >> 5;
    const float* xr = x + (size_t)row*DIM;
    const float* rr = r + (size_t)row*DIM;

    float s = 0.f;
    for (int i = tid; i < DIM; i += 256) { float v = xr[i] + rr[i]; buf[i] = v; s += v; }
    #pragma unroll
    for (int off = 16; off; off >>= 1) s += __shfl_xor_sync(0xffffffffu, s, off);
    if (lane == 0) red1[w] = s;
    __syncthreads();
    float tot = 0.f;
    #pragma unroll
    for (int i = 0; i < 8; i++) tot += red1[i];
    float mu = tot * (1.f / DIM);

    float vsum = 0.f;
    for (int i = tid; i < DIM; i += 256) { float d = buf[i] - mu; vsum += d*d; }
    #pragma unroll
    for (int off = 16; off; off >>= 1) vsum += __shfl_xor_sync(0xffffffffu, vsum, off);
    if (lane == 0) red2[w] = vsum;
    __syncthreads();
    float vtot = 0.f;
    #pragma unroll
    for (int i = 0; i < 8; i++) vtot += red2[i];
    float inv = rsqrtf(vtot * (1.f / DIM) + 1e-5f);

    float* orow = out + (size_t)row*DIM;
    for (int i = tid; i < DIM; i += 256)
        orow[i] = (buf[i] - mu) * inv * sc[i] + bi[i];
}

// ---------------- softmax: padded logits -> d_out ----------------
__global__ void softmax_rows(const float* __restrict__ in, float* __restrict__ out)
{
    int row = blockIdx.x, tid = threadIdx.x, lane = tid & 31, w = tid >> 5;
    const float* p = in + (size_t)row * NPADV;
    float* q = out + (size_t)row * VOC;
    __shared__ float smm[8], sss[8];

    float m = -INFINITY, s = 0.f;
    for (int i = tid; i < VOC; i += 256) {
        float xv = p[i];
        if (xv > m) { s = s * expf(m - xv) + 1.f; m = xv; }
        else        { s += expf(xv - m); }
    }
    #pragma unroll
    for (int off = 16; off; off >>= 1) {
        float m2 = __shfl_xor_sync(0xffffffffu, m, off);
        float s2 = __shfl_xor_sync(0xffffffffu, s, off);
        float mn = fmaxf(m, m2);
        s = s * expf(m - mn) + s2 * expf(m2 - mn);
        m = mn;
    }
    if (lane == 0) { smm[w] = m; sss[w] = s; }
    __syncthreads();
    if (tid == 0) {
        float M = smm[0], Sv = sss[0];
        #pragma unroll
        for (int i = 1; i < 8; i++) {
            float m2 = smm[i], s2 = sss[i];
            float mn = fmaxf(M, m2);
            Sv = Sv * expf(M - mn) + s2 * expf(m2 - mn);
            M = mn;
        }
        smm[0] = M; sss[0] = 1.f / Sv;
    }
    __syncthreads();
    float M = smm[0], inv = sss[0];
    for (int i = tid; i < VOC; i += 256)
        q[i] = expf(p[i] - M) * inv;
}

// ---------------- host driver ----------------
extern "C" void kernel_launch(void* const* d_in, const int* in_sizes, int n_in,
                              void* d_out, int out_size)
{
    const float* img   = (const float*)d_in[0];
    const int*   tok   = (const int*)  d_in[1];
    const int*   tmask = (const int*)  d_in[2];
    const float* temb  = (const float*)d_in[3];
    const float* sep   = (const float*)d_in[4];
    const float* Wq    = (const float*)d_in[5];
    const float* bq    = (const float*)d_in[6];
    const float* Wk    = (const float*)d_in[7];
    const float* bk    = (const float*)d_in[8];
    const float* Wv    = (const float*)d_in[9];
    const float* bv    = (const float*)d_in[10];
    const float* ln1s  = (const float*)d_in[11];
    const float* ln1b  = (const float*)d_in[12];
    const float* W1    = (const float*)d_in[13];
    const float* b1    = (const float*)d_in[14];
    const float* W2    = (const float*)d_in[15];
    const float* b2    = (const float*)d_in[16];
    const float* ln2s  = (const float*)d_in[17];
    const float* ln2b  = (const float*)d_in[18];
    const float* Wout  = (const float*)d_in[19];
    const float* bout  = (const float*)d_in[20];
    float* out = (float*)d_out;

    float *px, *pqkv, *po, *pff, *pt, *pb, *plog, *pa, *pbt;
    cudaGetSymbolAddress((void**)&px,   g_x);
    cudaGetSymbolAddress((void**)&pqkv, g_qkv);
    cudaGetSymbolAddress((void**)&po,   g_o);
    cudaGetSymbolAddress((void**)&pff,  g_ff);
    cudaGetSymbolAddress((void**)&pt,   g_t);
    cudaGetSymbolAddress((void**)&pb,   g_b);
    cudaGetSymbolAddress((void**)&plog, g_logits);
    cudaGetSymbolAddress((void**)&pa,   g_a);
    cudaGetSymbolAddress((void**)&pbt,  g_bt);

    const int ATTN_SMEM = (SEQ*KSTR*2 + 8*64 + 8*224) * 4 + 256;
    cudaFuncSetAttribute(attn_kernel, cudaFuncAttributeMaxDynamicSharedMemorySize, ATTN_SMEM);
    cudaFuncSetAttribute(gemm_mma, cudaFuncAttributeMaxDynamicSharedMemorySize, DSMEM);

    embed_kernel<<<MROWS, 256>>>(img, tok, temb, sep, px);

    #define ACONV(src, K)  a_convert<<<(int)(((size_t)MPAD*(K) + 255)/256), 256>>>(src, MROWS, K)
    #define GEMM(bias, C, K, ldc, Nreal, Npad, relu) \
        gemm_mma<<<dim3(MPAD/128, (Npad)/128), 256, DSMEM>>>(pa, pbt, bias, C, K, ldc, Nreal, MROWS, relu)

    for (int l = 0; l < NL; l++) {
        const size_t woff = (size_t)l * NH * DIM * HD;
        // QKV
        qkvw_convert<<<(QKVW*DIM + 255)/256, 256>>>(Wq + woff, Wk + woff, Wv + woff,
                                                    bq + (size_t)l*DIM, bk + (size_t)l*DIM,
                                                    bv + (size_t)l*DIM);
        ACONV(px, DIM);
        GEMM(pb, pqkv, DIM, QKVW, QKVW, QKVW, 0);
        attn_kernel<<<BATCH*NH*4, 256, ATTN_SMEM>>>(pqkv, tmask, po);
        add_ln_kernel<<<MROWS, 256>>>(px, po, ln1s + (size_t)l*DIM, ln1b + (size_t)l*DIM, px);
        // FFN1
        ACONV(px, DIM);
        wt_convert<<<dim3(FF/32, DIM/32), dim3(32, 8)>>>(W1 + (size_t)l*DIM*FF, DIM, FF);
        GEMM(b1 + (size_t)l*FF, pff, DIM, FF, FF, FF, 1);
        // FFN2
        ACONV(pff, FF);
        wt_convert<<<dim3(DIM/32, FF/32), dim3(32, 8)>>>(W2 + (size_t)l*FF*DIM, FF, DIM);
        GEMM(b2 + (size_t)l*DIM, pt, FF, DIM, DIM, DIM, 0);
        add_ln_kernel<<<MROWS, 256>>>(px, pt, ln2s + (size_t)l*DIM, ln2b + (size_t)l*DIM, px);
    }

    // vocab projection (padded logits) + softmax into d_out
    ACONV(px, DIM);
    wt_convert<<<dim3(NPADV/32, DIM/32), dim3(32, 8)>>>(Wout, DIM, VOC);
    GEMM(bout, plog, DIM, NPADV, VOC, NPADV, 0);
    softmax_rows<<<MROWS, 256>>>(plog, out);
}

// round 10
// speedup vs baseline: 1.4914x; 1.0761x over previous
#include <cuda_runtime.h>
#include <cuda_bf16.h>
#include <math.h>
#include <stdint.h>

// ---------------- problem constants ----------------
#define BATCH 16
#define IMG   197
#define TXT   24
#define SEQ   222
#define DIM   768
#define NH    12
#define HD    64
#define NL    6
#define VOC   50257
#define FF    3072
#define MROWS (BATCH*SEQ)  // 3552
#define QKVW  (3*DIM)      // 2304
#define MPAD  3584         // 28 * 128
#define NPADV 50432        // 394 * 128

// ---------------- GEMM tiling (tf32 mma.sync + ldmatrix, 3-stage) ----------------
#define TKC    32                 // K per stage (4 k8-steps)
#define ASTRF  36                 // smem row stride in floats -> conflict-free ldmatrix
#define MATSZF (128*ASTRF*4)      // 18432 B per matrix tile
#define STSZ   (2*MATSZF)         // A + B = 36864 B
#define NSTG   3
#define DSMEM  (NSTG*STSZ)        // 110592 B (x2 CTAs = 221184 < 228KB)

// ---------------- device scratch ----------------
__device__ float g_x   [MROWS*DIM];
__device__ float g_qkv [MROWS*QKVW];
__device__ float g_o   [MROWS*DIM];
__device__ float g_t   [MROWS*DIM];
__device__ float g_b   [QKVW];
__device__ float g_a   [MPAD*DIM];           // tf32 activations, K=768 GEMMs
__device__ float g_a2  [MPAD*FF];            // tf32 FFN1 output, K=3072 GEMM
__device__ float g_bt  [(size_t)NPADV*DIM];  // tf32 weights^T [Npad,K]
__device__ float g_logits[(size_t)MROWS*NPADV];

// ---------------- PTX helpers ----------------
__device__ __forceinline__ uint32_t s2u(const void* p) {
    uint32_t a;
    asm("{ .reg .u64 t; cvta.to.shared.u64 t, %1; cvt.u32.u64 %0, t; }" : "=r"(a) : "l"(p));
    return a;
}
#define CP16(dst, src)   asm volatile("cp.async.cg.shared.global [%0], [%1], 16;" :: "r"(dst), "l"(src))
#define CP_COMMIT()      asm volatile("cp.async.commit_group;" ::: "memory")
#define CP_WAIT(n)       asm volatile("cp.async.wait_group %0;" :: "n"(n) : "memory")

__device__ __forceinline__ float tf32r(float v) {
    uint32_t o;
    asm("cvt.rna.tf32.f32 %0, %1;" : "=r"(o) : "f"(v));
    return __uint_as_float(o);
}
__device__ __forceinline__ void mma_tf32(float* c, const uint32_t* a, const uint32_t* b) {
    asm volatile(
        "mma.sync.aligned.m16n8k8.row.col.f32.tf32.tf32.f32 "
        "{%0,%1,%2,%3}, {%4,%5,%6,%7}, {%8,%9}, {%0,%1,%2,%3};"
        : "+f"(c[0]), "+f"(c[1]), "+f"(c[2]), "+f"(c[3])
        : "r"(a[0]), "r"(a[1]), "r"(a[2]), "r"(a[3]), "r"(b[0]), "r"(b[1]));
}
__device__ __forceinline__ void ldsm4(uint32_t* r, uint32_t addr) {
    asm volatile("ldmatrix.sync.aligned.m8n8.x4.shared.b16 {%0,%1,%2,%3}, [%4];"
                 : "=r"(r[0]), "=r"(r[1]), "=r"(r[2]), "=r"(r[3]) : "r"(addr));
}

// ---------------- embedding (writes fp32 x AND tf32 g_a) ----------------
__global__ void embed_kernel(const float* __restrict__ img, const int* __restrict__ tok,
                             const float* __restrict__ temb, const float* __restrict__ sep,
                             float* __restrict__ x, float* __restrict__ ga)
{
    int row = blockIdx.x;
    int b = row / SEQ, s = row % SEQ;
    const float* src;
    if (s < IMG)       src = img + (size_t)(b*IMG + s)*DIM;
    else if (s == IMG) src = sep;
    else               src = temb + (size_t)tok[b*TXT + (s-IMG-1)] * DIM;
    float* dst = x + (size_t)row*DIM;
    float* da  = ga + (size_t)row*DIM;
    for (int i = threadIdx.x; i < DIM; i += blockDim.x) {
        float v = src[i];
        dst[i] = v;
        da[i]  = tf32r(v);
    }
}

// ---------------- weight transpose+round ----------------
__global__ void wt_convert(const float* __restrict__ src, int K, int N)
{
    __shared__ float t[32][33];
    int n0 = blockIdx.x*32, k0 = blockIdx.y*32;
    int tx = threadIdx.x, ty = threadIdx.y;
    #pragma unroll
    for (int j = 0; j < 32; j += 8) {
        int n = n0 + tx;
        t[ty+j][tx] = (n < N) ? src[(size_t)(k0+ty+j)*N + n] : 0.f;
    }
    __syncthreads();
    #pragma unroll
    for (int j = 0; j < 32; j += 8) {
        int n = n0 + ty + j, k = k0 + tx;
        g_bt[(size_t)n*K + k] = tf32r(t[tx][ty+j]);
    }
}

// ---------------- QKV weight gather+round ----------------
__global__ void qkvw_convert(const float* __restrict__ Wq, const float* __restrict__ Wk,
                             const float* __restrict__ Wv,
                             const float* __restrict__ bq, const float* __restrict__ bk,
                             const float* __restrict__ bv)
{
    int idx = blockIdx.x*256 + threadIdx.x;
    if (idx < QKVW*DIM) {
        int c = idx / DIM, d = idx % DIM;
        int which = c / DIM, w2 = c % DIM;
        int h = w2 >> 6, e = w2 & 63;
        const float* W = (which == 0) ? Wq : (which == 1) ? Wk : Wv;
        g_bt[idx] = tf32r(W[(size_t)h*DIM*HD + (size_t)d*HD + e]);
    }
    if (idx < QKVW) {
        int which = idx / DIM, cc = idx % DIM;
        const float* bb = (which == 0) ? bq : (which == 1) ? bk : bv;
        g_b[idx] = bb[cc];
    }
}

// ---------------- tf32 mma.sync GEMM, 3-stage cp.async, ldmatrix frags ----------------
// CTA 128x128, 8 warps of 64x32, 2 CTAs/SM. tf32out: store tf32r(value) (for FFN1 -> g_a2).
__global__ __launch_bounds__(256, 2)
void gemm_mma(const float* __restrict__ Aa, const float* __restrict__ Bt,
              const float* __restrict__ bias, float* __restrict__ C,
              int K, int ldc, int Nreal, int Mreal, int relu, int tf32out)
{
    extern __shared__ char dsm[];
    const int tid = threadIdx.x;
    const int wid = tid >> 5, lane = tid & 31;
    const int m0 = blockIdx.x * 128, n0 = blockIdx.y * 128;
    const int wm = wid >> 2, wn = wid & 3;
    const int g = lane >> 2, t = lane & 3;
    const int nk = K / TKC;
    const uint32_t sb = s2u(dsm);

    const uint32_t aLaneOff =
        (uint32_t)(((wm*64 + ((lane & 8) ? 8 : 0) + (lane & 7)) * ASTRF)
                   + ((lane & 16) ? 4 : 0)) * 4;
    const uint32_t bLaneOff =
        (uint32_t)(((wn*32 + ((lane & 16) ? 8 : 0) + (lane & 7)) * ASTRF)
                   + ((lane & 8) ? 4 : 0)) * 4;

    float acc[4][4][4];
    #pragma unroll
    for (int mi = 0; mi < 4; mi++)
        #pragma unroll
        for (int ni = 0; ni < 4; ni++)
            #pragma unroll
            for (int r = 0; r < 4; r++) acc[mi][ni][r] = 0.f;

    // stage loader: A 128x32 + B 128x32 fp32, rows padded to 36 floats. 2048 chunks, 8/thread.
    #define LOAD_ST(st, kc) do {                                                     \
        int k0_ = (kc) * TKC;                                                        \
        _Pragma("unroll")                                                            \
        for (int c_ = tid; c_ < 2048; c_ += 256) {                                   \
            int isB_ = (c_ >= 1024);                                                 \
            int cc_  = c_ & 1023;                                                    \
            int row_ = cc_ >> 3, c4_ = cc_ & 7;                                      \
            const float* sp_ = (isB_ ? Bt + (size_t)(n0 + row_) * K                  \
                                     : Aa + (size_t)(m0 + row_) * K) + k0_ + c4_*4;  \
            uint32_t dst_ = sb + (st)*STSZ + (isB_ ? MATSZF : 0) + row_*144 + c4_*16;\
            CP16(dst_, sp_);                                                         \
        }                                                                            \
        CP_COMMIT();                                                                 \
    } while (0)

    LOAD_ST(0, 0);
    LOAD_ST(1, 1);

    int cur = 0, nx2 = 2;
    for (int kc = 0; kc < nk; kc++) {
        if (kc < nk - 1) CP_WAIT(1); else CP_WAIT(0);
        __syncthreads();
        if (kc + 2 < nk) LOAD_ST(nx2, kc + 2);      // overlaps compute below

        const uint32_t stg = sb + cur*STSZ;
        const uint32_t aB = stg + aLaneOff;
        const uint32_t bB = stg + MATSZF + bLaneOff;

        #pragma unroll
        for (int ks = 0; ks < 4; ks++) {
            const uint32_t kof = ks * 32;           // ks*8 words * 4B
            uint32_t af[16], bf[16];
            #pragma unroll
            for (int mi = 0; mi < 4; mi++)
                ldsm4(af + mi*4, aB + mi*(16*ASTRF*4) + kof);
            ldsm4(bf,     bB + kof);
            ldsm4(bf + 4, bB + 16*ASTRF*4 + kof);
            #pragma unroll
            for (int mi = 0; mi < 4; mi++) {
                #pragma unroll
                for (int ni = 0; ni < 4; ni++)
                    mma_tf32(acc[mi][ni], af + mi*4, bf + ni*2);
            }
        }
        cur = (cur == 2) ? 0 : cur + 1;
        nx2 = (nx2 == 2) ? 0 : nx2 + 1;
    }

    // epilogue
    #pragma unroll
    for (int mi = 0; mi < 4; mi++) {
        int gm0 = m0 + wm*64 + mi*16 + g;
        #pragma unroll
        for (int ni = 0; ni < 4; ni++) {
            int gn = n0 + wn*32 + ni*8 + t*2;
            float bx = (gn     < Nreal) ? bias[gn]     : 0.f;
            float by = (gn + 1 < Nreal) ? bias[gn + 1] : 0.f;
            float c0 = acc[mi][ni][0] + bx, c1 = acc[mi][ni][1] + by;
            float c2 = acc[mi][ni][2] + bx, c3 = acc[mi][ni][3] + by;
            if (relu) {
                c0 = fmaxf(c0, 0.f); c1 = fmaxf(c1, 0.f);
                c2 = fmaxf(c2, 0.f); c3 = fmaxf(c3, 0.f);
            }
            if (tf32out) {
                c0 = tf32r(c0); c1 = tf32r(c1); c2 = tf32r(c2); c3 = tf32r(c3);
            }
            if (gm0 < Mreal)
                *reinterpret_cast<float2*>(C + (size_t)gm0*ldc + gn) = make_float2(c0, c1);
            if (gm0 + 8 < Mreal)
                *reinterpret_cast<float2*>(C + (size_t)(gm0+8)*ldc + gn) = make_float2(c2, c3);
        }
    }
}

// ---------------- attention: 4-way q split per (b,h) ----------------
#define KSTR 65
__global__ void attn_kernel(const float* __restrict__ qkv,
                            const int* __restrict__ tmask,
                            float* __restrict__ o)
{
    int bh = blockIdx.x >> 2, z = blockIdx.x & 3;
    int b = bh / NH, h = bh % NH;
    extern __shared__ float sm[];
    float* ks = sm;
    float* vs = ks + SEQ*KSTR;
    float* qs = vs + SEQ*KSTR;
    float* sc = qs + 8*64;
    unsigned char* valid = (unsigned char*)(sc + 8*224);

    int tid = threadIdx.x, lane = tid & 31, w = tid >> 5;
    const float* base = qkv + (size_t)b * SEQ * QKVW;

    for (int i = tid; i < SEQ*HD; i += 256) {
        int t = i >> 6, e = i & 63;
        ks[t*KSTR + e] = base[(size_t)t*QKVW +   DIM + h*64 + e];
        vs[t*KSTR + e] = base[(size_t)t*QKVW + 2*DIM + h*64 + e];
    }
    for (int t = tid; t < SEQ; t += 256)
        valid[t] = (t < SEQ - TXT) ? 1 : (tmask[b*TXT + t - (SEQ-TXT)] != 0);
    __syncthreads();

    float* myq  = qs + w*64;
    float* mysc = sc + w*224;
    for (int s = (w << 2) + z; s < SEQ; s += 32) {
        myq[lane]      = base[(size_t)s*QKVW + h*64 + lane];
        myq[lane + 32] = base[(size_t)s*QKVW + h*64 + lane + 32];
        __syncwarp();

        float lmax = -INFINITY;
        for (int t = lane; t <= s; t += 32) {
            float d = -INFINITY;
            if (valid[t]) {
                d = 0.f;
                #pragma unroll
                for (int e = 0; e < 64; e++) d += myq[e] * ks[t*KSTR + e];
                d *= 0.125f;
            }
            mysc[t] = d;
            lmax = fmaxf(lmax, d);
        }
        #pragma unroll
        for (int off = 16; off; off >>= 1)
            lmax = fmaxf(lmax, __shfl_xor_sync(0xffffffffu, lmax, off));

        float lsum = 0.f;
        for (int t = lane; t <= s; t += 32) {
            float p = expf(mysc[t] - lmax);
            mysc[t] = p;
            lsum += p;
        }
        #pragma unroll
        for (int off = 16; off; off >>= 1)
            lsum += __shfl_xor_sync(0xffffffffu, lsum, off);
        float inv = 1.f / lsum;
        __syncwarp();

        float acc0 = 0.f, acc1 = 0.f;
        for (int t = 0; t <= s; t++) {
            float p = mysc[t];
            acc0 += p * vs[t*KSTR + lane];
            acc1 += p * vs[t*KSTR + lane + 32];
        }
        float* orow = o + (size_t)(b*SEQ + s)*DIM + h*64;
        orow[lane]      = acc0 * inv;
        orow[lane + 32] = acc1 * inv;
        __syncwarp();
    }
}

// ---------------- residual add + LayerNorm (writes fp32 out AND tf32 ga) ----------------
__global__ void add_ln_kernel(const float* __restrict__ x, const float* __restrict__ r,
                              const float* __restrict__ sc, const float* __restrict__ bi,
                              float* __restrict__ out, float* __restrict__ ga)
{
    __shared__ float buf[DIM];
    __shared__ float red1[8], red2[8];
    int row = blockIdx.x, tid = threadIdx.x, lane = tid & 31, w = tid >> 5;
    const float* xr = x + (size_t)row*DIM;
    const float* rr = r + (size_t)row*DIM;

    float s = 0.f;
    for (int i = tid; i < DIM; i += 256) { float v = xr[i] + rr[i]; buf[i] = v; s += v; }
    #pragma unroll
    for (int off = 16; off; off >>= 1) s += __shfl_xor_sync(0xffffffffu, s, off);
    if (lane == 0) red1[w] = s;
    __syncthreads();
    float tot = 0.f;
    #pragma unroll
    for (int i = 0; i < 8; i++) tot += red1[i];
    float mu = tot * (1.f / DIM);

    float vsum = 0.f;
    for (int i = tid; i < DIM; i += 256) { float d = buf[i] - mu; vsum += d*d; }
    #pragma unroll
    for (int off = 16; off; off >>= 1) vsum += __shfl_xor_sync(0xffffffffu, vsum, off);
    if (lane == 0) red2[w] = vsum;
    __syncthreads();
    float vtot = 0.f;
    #pragma unroll
    for (int i = 0; i < 8; i++) vtot += red2[i];
    float inv = rsqrtf(vtot * (1.f / DIM) + 1e-5f);

    float* orow = out + (size_t)row*DIM;
    float* arow = ga  + (size_t)row*DIM;
    for (int i = tid; i < DIM; i += 256) {
        float v = (buf[i] - mu) * inv * sc[i] + bi[i];
        orow[i] = v;
        arow[i] = tf32r(v);
    }
}

// ---------------- softmax: padded logits -> d_out ----------------
__global__ void softmax_rows(const float* __restrict__ in, float* __restrict__ out)
{
    int row = blockIdx.x, tid = threadIdx.x, lane = tid & 31, w = tid >> 5;
    const float* p = in + (size_t)row * NPADV;
    float* q = out + (size_t)row * VOC;
    __shared__ float smm[8], sss[8];

    float m = -INFINITY, s = 0.f;
    for (int i = tid; i < VOC; i += 256) {
        float xv = p[i];
        if (xv > m) { s = s * expf(m - xv) + 1.f; m = xv; }
        else        { s += expf(xv - m); }
    }
    #pragma unroll
    for (int off = 16; off; off >>= 1) {
        float m2 = __shfl_xor_sync(0xffffffffu, m, off);
        float s2 = __shfl_xor_sync(0xffffffffu, s, off);
        float mn = fmaxf(m, m2);
        s = s * expf(m - mn) + s2 * expf(m2 - mn);
        m = mn;
    }
    if (lane == 0) { smm[w] = m; sss[w] = s; }
    __syncthreads();
    if (tid == 0) {
        float M = smm[0], Sv = sss[0];
        #pragma unroll
        for (int i = 1; i < 8; i++) {
            float m2 = smm[i], s2 = sss[i];
            float mn = fmaxf(M, m2);
            Sv = Sv * expf(M - mn) + s2 * expf(m2 - mn);
            M = mn;
        }
        smm[0] = M; sss[0] = 1.f / Sv;
    }
    __syncthreads();
    float M = smm[0], inv = sss[0];
    for (int i = tid; i < VOC; i += 256)
        q[i] = expf(p[i] - M) * inv;
}

// ---------------- host driver ----------------
extern "C" void kernel_launch(void* const* d_in, const int* in_sizes, int n_in,
                              void* d_out, int out_size)
{
    const float* img   = (const float*)d_in[0];
    const int*   tok   = (const int*)  d_in[1];
    const int*   tmask = (const int*)  d_in[2];
    const float* temb  = (const float*)d_in[3];
    const float* sep   = (const float*)d_in[4];
    const float* Wq    = (const float*)d_in[5];
    const float* bq    = (const float*)d_in[6];
    const float* Wk    = (const float*)d_in[7];
    const float* bk    = (const float*)d_in[8];
    const float* Wv    = (const float*)d_in[9];
    const float* bv    = (const float*)d_in[10];
    const float* ln1s  = (const float*)d_in[11];
    const float* ln1b  = (const float*)d_in[12];
    const float* W1    = (const float*)d_in[13];
    const float* b1    = (const float*)d_in[14];
    const float* W2    = (const float*)d_in[15];
    const float* b2    = (const float*)d_in[16];
    const float* ln2s  = (const float*)d_in[17];
    const float* ln2b  = (const float*)d_in[18];
    const float* Wout  = (const float*)d_in[19];
    const float* bout  = (const float*)d_in[20];
    float* out = (float*)d_out;

    float *px, *pqkv, *po, *pt, *pb, *plog, *pa, *pa2, *pbt;
    cudaGetSymbolAddress((void**)&px,   g_x);
    cudaGetSymbolAddress((void**)&pqkv, g_qkv);
    cudaGetSymbolAddress((void**)&po,   g_o);
    cudaGetSymbolAddress((void**)&pt,   g_t);
    cudaGetSymbolAddress((void**)&pb,   g_b);
    cudaGetSymbolAddress((void**)&plog, g_logits);
    cudaGetSymbolAddress((void**)&pa,   g_a);
    cudaGetSymbolAddress((void**)&pa2,  g_a2);
    cudaGetSymbolAddress((void**)&pbt,  g_bt);

    const int ATTN_SMEM = (SEQ*KSTR*2 + 8*64 + 8*224) * 4 + 256;
    cudaFuncSetAttribute(attn_kernel, cudaFuncAttributeMaxDynamicSharedMemorySize, ATTN_SMEM);
    cudaFuncSetAttribute(gemm_mma, cudaFuncAttributeMaxDynamicSharedMemorySize, DSMEM);

    embed_kernel<<<MROWS, 256>>>(img, tok, temb, sep, px, pa);

    #define GEMM(A, bias, C, K, ldc, Nreal, Npad, relu, tfo) \
        gemm_mma<<<dim3(MPAD/128, (Npad)/128), 256, DSMEM>>>(A, pbt, bias, C, K, ldc, Nreal, MROWS, relu, tfo)

    for (int l = 0; l < NL; l++) {
        const size_t woff = (size_t)l * NH * DIM * HD;
        // QKV  (A = g_a, written by embed / previous add_ln2)
        qkvw_convert<<<(QKVW*DIM + 255)/256, 256>>>(Wq + woff, Wk + woff, Wv + woff,
                                                    bq + (size_t)l*DIM, bk + (size_t)l*DIM,
                                                    bv + (size_t)l*DIM);
        GEMM(pa, pb, pqkv, DIM, QKVW, QKVW, QKVW, 0, 0);
        attn_kernel<<<BATCH*NH*4, 256, ATTN_SMEM>>>(pqkv, tmask, po);
        add_ln_kernel<<<MROWS, 256>>>(px, po, ln1s + (size_t)l*DIM, ln1b + (size_t)l*DIM, px, pa);
        // FFN1: writes tf32 relu output directly to g_a2
        wt_convert<<<dim3(FF/32, DIM/32), dim3(32, 8)>>>(W1 + (size_t)l*DIM*FF, DIM, FF);
        GEMM(pa, b1 + (size_t)l*FF, pa2, DIM, FF, FF, FF, 1, 1);
        // FFN2 (A = g_a2)
        wt_convert<<<dim3(DIM/32, FF/32), dim3(32, 8)>>>(W2 + (size_t)l*FF*DIM, FF, DIM);
        GEMM(pa2, b2 + (size_t)l*DIM, pt, FF, DIM, DIM, DIM, 0, 0);
        add_ln_kernel<<<MROWS, 256>>>(px, pt, ln2s + (size_t)l*DIM, ln2b + (size_t)l*DIM, px, pa);
    }

    // vocab projection (padded logits) + softmax into d_out
    wt_convert<<<dim3(NPADV/32, DIM/32), dim3(32, 8)>>>(Wout, DIM, VOC);
    GEMM(pa, bout, plog, DIM, NPADV, VOC, NPADV, 0, 0);
    softmax_rows<<<MROWS, 256>>>(plog, out);
}

// round 11
// speedup vs baseline: 1.5099x; 1.0124x over previous
#include <cuda_runtime.h>
#include <cuda_bf16.h>
#include <math.h>
#include <stdint.h>

// ---------------- problem constants ----------------
#define BATCH 16
#define IMG   197
#define TXT   24
#define SEQ   222
#define DIM   768
#define NH    12
#define HD    64
#define NL    6
#define VOC   50257
#define FF    3072
#define MROWS (BATCH*SEQ)  // 3552
#define QKVW  (3*DIM)      // 2304
#define MPAD  3584         // 28 * 128
#define NPADV 50432        // 394 * 128

// ---------------- GEMM tiling (tf32 mma.sync + ldmatrix, 3-stage) ----------------
#define TKC    32                 // K per stage (4 k8-steps)
#define ASTRF  36                 // smem row stride in floats -> conflict-free ldmatrix
#define MATSZF (128*ASTRF*4)      // 18432 B per matrix tile
#define STSZ   (2*MATSZF)         // A + B = 36864 B
#define NSTG   3
#define DSMEM  (NSTG*STSZ)        // 110592 B (x2 CTAs = 221184 < 228KB)

// ---------------- device scratch ----------------
__device__ float g_x   [MROWS*DIM];
__device__ float g_qkv [MROWS*QKVW];
__device__ float g_o   [MROWS*DIM];
__device__ float g_t   [MROWS*DIM];
__device__ float g_b   [QKVW];
__device__ float g_a   [MPAD*DIM];           // tf32 activations, K=768 GEMMs
__device__ float g_a2  [MPAD*FF];            // tf32 FFN1 output, K=3072 GEMM
__device__ float g_bt  [(size_t)NPADV*DIM];  // tf32 weights^T [Npad,K]
__device__ float g_logits[(size_t)MROWS*NPADV];

// ---------------- PTX helpers ----------------
__device__ __forceinline__ uint32_t s2u(const void* p) {
    uint32_t a;
    asm("{ .reg .u64 t; cvta.to.shared.u64 t, %1; cvt.u32.u64 %0, t; }" : "=r"(a) : "l"(p));
    return a;
}
#define CP16(dst, src)   asm volatile("cp.async.cg.shared.global [%0], [%1], 16;" :: "r"(dst), "l"(src))
#define CP_COMMIT()      asm volatile("cp.async.commit_group;" ::: "memory")
#define CP_WAIT(n)       asm volatile("cp.async.wait_group %0;" :: "n"(n) : "memory")

__device__ __forceinline__ float tf32r(float v) {
    uint32_t o;
    asm("cvt.rna.tf32.f32 %0, %1;" : "=r"(o) : "f"(v));
    return __uint_as_float(o);
}
__device__ __forceinline__ void mma_tf32(float* c, const uint32_t* a, const uint32_t* b) {
    asm volatile(
        "mma.sync.aligned.m16n8k8.row.col.f32.tf32.tf32.f32 "
        "{%0,%1,%2,%3}, {%4,%5,%6,%7}, {%8,%9}, {%0,%1,%2,%3};"
        : "+f"(c[0]), "+f"(c[1]), "+f"(c[2]), "+f"(c[3])
        : "r"(a[0]), "r"(a[1]), "r"(a[2]), "r"(a[3]), "r"(b[0]), "r"(b[1]));
}
__device__ __forceinline__ void ldsm4(uint32_t* r, uint32_t addr) {
    asm volatile("ldmatrix.sync.aligned.m8n8.x4.shared.b16 {%0,%1,%2,%3}, [%4];"
                 : "=r"(r[0]), "=r"(r[1]), "=r"(r[2]), "=r"(r[3]) : "r"(addr));
}

// ---------------- embedding (writes fp32 x AND tf32 g_a) ----------------
__global__ void embed_kernel(const float* __restrict__ img, const int* __restrict__ tok,
                             const float* __restrict__ temb, const float* __restrict__ sep,
                             float* __restrict__ x, float* __restrict__ ga)
{
    int row = blockIdx.x;
    int b = row / SEQ, s = row % SEQ;
    const float* src;
    if (s < IMG)       src = img + (size_t)(b*IMG + s)*DIM;
    else if (s == IMG) src = sep;
    else               src = temb + (size_t)tok[b*TXT + (s-IMG-1)] * DIM;
    float* dst = x + (size_t)row*DIM;
    float* da  = ga + (size_t)row*DIM;
    for (int i = threadIdx.x; i < DIM; i += blockDim.x) {
        float v = src[i];
        dst[i] = v;
        da[i]  = tf32r(v);
    }
}

// ---------------- weight transpose+round ----------------
__global__ void wt_convert(const float* __restrict__ src, int K, int N)
{
    __shared__ float t[32][33];
    int n0 = blockIdx.x*32, k0 = blockIdx.y*32;
    int tx = threadIdx.x, ty = threadIdx.y;
    #pragma unroll
    for (int j = 0; j < 32; j += 8) {
        int n = n0 + tx;
        t[ty+j][tx] = (n < N) ? src[(size_t)(k0+ty+j)*N + n] : 0.f;
    }
    __syncthreads();
    #pragma unroll
    for (int j = 0; j < 32; j += 8) {
        int n = n0 + ty + j, k = k0 + tx;
        g_bt[(size_t)n*K + k] = tf32r(t[tx][ty+j]);
    }
}

// ---------------- QKV weight gather+round ----------------
__global__ void qkvw_convert(const float* __restrict__ Wq, const float* __restrict__ Wk,
                             const float* __restrict__ Wv,
                             const float* __restrict__ bq, const float* __restrict__ bk,
                             const float* __restrict__ bv)
{
    int idx = blockIdx.x*256 + threadIdx.x;
    if (idx < QKVW*DIM) {
        int c = idx / DIM, d = idx % DIM;
        int which = c / DIM, w2 = c % DIM;
        int h = w2 >> 6, e = w2 & 63;
        const float* W = (which == 0) ? Wq : (which == 1) ? Wk : Wv;
        g_bt[idx] = tf32r(W[(size_t)h*DIM*HD + (size_t)d*HD + e]);
    }
    if (idx < QKVW) {
        int which = idx / DIM, cc = idx % DIM;
        const float* bb = (which == 0) ? bq : (which == 1) ? bk : bv;
        g_b[idx] = bb[cc];
    }
}

// ---------------- tf32 mma.sync GEMM, 3-stage cp.async, ldmatrix frags ----------------
__global__ __launch_bounds__(256, 2)
void gemm_mma(const float* __restrict__ Aa, const float* __restrict__ Bt,
              const float* __restrict__ bias, float* __restrict__ C,
              int K, int ldc, int Nreal, int Mreal, int relu, int tf32out)
{
    extern __shared__ char dsm[];
    const int tid = threadIdx.x;
    const int wid = tid >> 5, lane = tid & 31;
    const int m0 = blockIdx.x * 128, n0 = blockIdx.y * 128;
    const int wm = wid >> 2, wn = wid & 3;
    const int g = lane >> 2, t = lane & 3;
    const int nk = K / TKC;
    const uint32_t sb = s2u(dsm);

    const uint32_t aLaneOff =
        (uint32_t)(((wm*64 + ((lane & 8) ? 8 : 0) + (lane & 7)) * ASTRF)
                   + ((lane & 16) ? 4 : 0)) * 4;
    const uint32_t bLaneOff =
        (uint32_t)(((wn*32 + ((lane & 16) ? 8 : 0) + (lane & 7)) * ASTRF)
                   + ((lane & 8) ? 4 : 0)) * 4;

    float acc[4][4][4];
    #pragma unroll
    for (int mi = 0; mi < 4; mi++)
        #pragma unroll
        for (int ni = 0; ni < 4; ni++)
            #pragma unroll
            for (int r = 0; r < 4; r++) acc[mi][ni][r] = 0.f;

    #define LOAD_ST(st, kc) do {                                                     \
        int k0_ = (kc) * TKC;                                                        \
        _Pragma("unroll")                                                            \
        for (int c_ = tid; c_ < 2048; c_ += 256) {                                   \
            int isB_ = (c_ >= 1024);                                                 \
            int cc_  = c_ & 1023;                                                    \
            int row_ = cc_ >> 3, c4_ = cc_ & 7;                                      \
            const float* sp_ = (isB_ ? Bt + (size_t)(n0 + row_) * K                  \
                                     : Aa + (size_t)(m0 + row_) * K) + k0_ + c4_*4;  \
            uint32_t dst_ = sb + (st)*STSZ + (isB_ ? MATSZF : 0) + row_*144 + c4_*16;\
            CP16(dst_, sp_);                                                         \
        }                                                                            \
        CP_COMMIT();                                                                 \
    } while (0)

    LOAD_ST(0, 0);
    LOAD_ST(1, 1);

    int cur = 0, nx2 = 2;
    for (int kc = 0; kc < nk; kc++) {
        if (kc < nk - 1) CP_WAIT(1); else CP_WAIT(0);
        __syncthreads();
        if (kc + 2 < nk) LOAD_ST(nx2, kc + 2);

        const uint32_t stg = sb + cur*STSZ;
        const uint32_t aB = stg + aLaneOff;
        const uint32_t bB = stg + MATSZF + bLaneOff;

        #pragma unroll
        for (int ks = 0; ks < 4; ks++) {
            const uint32_t kof = ks * 32;
            uint32_t af[16], bf[16];
            #pragma unroll
            for (int mi = 0; mi < 4; mi++)
                ldsm4(af + mi*4, aB + mi*(16*ASTRF*4) + kof);
            ldsm4(bf,     bB + kof);
            ldsm4(bf + 4, bB + 16*ASTRF*4 + kof);
            #pragma unroll
            for (int mi = 0; mi < 4; mi++) {
                #pragma unroll
                for (int ni = 0; ni < 4; ni++)
                    mma_tf32(acc[mi][ni], af + mi*4, bf + ni*2);
            }
        }
        cur = (cur == 2) ? 0 : cur + 1;
        nx2 = (nx2 == 2) ? 0 : nx2 + 1;
    }

    #pragma unroll
    for (int mi = 0; mi < 4; mi++) {
        int gm0 = m0 + wm*64 + mi*16 + g;
        #pragma unroll
        for (int ni = 0; ni < 4; ni++) {
            int gn = n0 + wn*32 + ni*8 + t*2;
            float bx = (gn     < Nreal) ? bias[gn]     : 0.f;
            float by = (gn + 1 < Nreal) ? bias[gn + 1] : 0.f;
            float c0 = acc[mi][ni][0] + bx, c1 = acc[mi][ni][1] + by;
            float c2 = acc[mi][ni][2] + bx, c3 = acc[mi][ni][3] + by;
            if (relu) {
                c0 = fmaxf(c0, 0.f); c1 = fmaxf(c1, 0.f);
                c2 = fmaxf(c2, 0.f); c3 = fmaxf(c3, 0.f);
            }
            if (tf32out) {
                c0 = tf32r(c0); c1 = tf32r(c1); c2 = tf32r(c2); c3 = tf32r(c3);
            }
            if (gm0 < Mreal)
                *reinterpret_cast<float2*>(C + (size_t)gm0*ldc + gn) = make_float2(c0, c1);
            if (gm0 + 8 < Mreal)
                *reinterpret_cast<float2*>(C + (size_t)(gm0+8)*ldc + gn) = make_float2(c2, c3);
        }
    }
}

// ---------------- attention: 1 block per (b,h), 512 threads / 16 warps ----------------
// K padded to stride 65 (t-indexed dot reads), V unpadded stride 64 (lane-indexed reads).
#define KSTR 65
#define AW   16   // warps per attention block
__global__ __launch_bounds__(512, 1)
void attn_kernel(const float* __restrict__ qkv,
                 const int* __restrict__ tmask,
                 float* __restrict__ o)
{
    int b = blockIdx.x / NH, h = blockIdx.x % NH;
    extern __shared__ float sm[];
    float* ks = sm;                         // SEQ*65
    float* vs = ks + SEQ*KSTR;              // SEQ*64
    float* qs = vs + SEQ*HD;                // AW*64
    float* sc = qs + AW*64;                 // AW*224
    unsigned char* valid = (unsigned char*)(sc + AW*224);

    int tid = threadIdx.x, lane = tid & 31, w = tid >> 5;
    const float* base = qkv + (size_t)b * SEQ * QKVW;

    for (int i = tid; i < SEQ*HD; i += 512) {
        int t = i >> 6, e = i & 63;
        ks[t*KSTR + e] = base[(size_t)t*QKVW +   DIM + h*64 + e];
        vs[t*HD   + e] = base[(size_t)t*QKVW + 2*DIM + h*64 + e];
    }
    for (int t = tid; t < SEQ; t += 512)
        valid[t] = (t < SEQ - TXT) ? 1 : (tmask[b*TXT + t - (SEQ-TXT)] != 0);
    __syncthreads();

    float* myq  = qs + w*64;
    float* mysc = sc + w*224;
    for (int s = w; s < SEQ; s += AW) {
        myq[lane]      = base[(size_t)s*QKVW + h*64 + lane];
        myq[lane + 32] = base[(size_t)s*QKVW + h*64 + lane + 32];
        __syncwarp();

        float lmax = -INFINITY;
        for (int t = lane; t <= s; t += 32) {
            float d = -INFINITY;
            if (valid[t]) {
                d = 0.f;
                #pragma unroll
                for (int e = 0; e < 64; e++) d += myq[e] * ks[t*KSTR + e];
                d *= 0.125f;
            }
            mysc[t] = d;
            lmax = fmaxf(lmax, d);
        }
        #pragma unroll
        for (int off = 16; off; off >>= 1)
            lmax = fmaxf(lmax, __shfl_xor_sync(0xffffffffu, lmax, off));

        float lsum = 0.f;
        for (int t = lane; t <= s; t += 32) {
            float p = expf(mysc[t] - lmax);
            mysc[t] = p;
            lsum += p;
        }
        #pragma unroll
        for (int off = 16; off; off >>= 1)
            lsum += __shfl_xor_sync(0xffffffffu, lsum, off);
        float inv = 1.f / lsum;
        __syncwarp();

        float acc0 = 0.f, acc1 = 0.f;
        for (int t = 0; t <= s; t++) {
            float p = mysc[t];
            acc0 += p * vs[t*HD + lane];
            acc1 += p * vs[t*HD + lane + 32];
        }
        float* orow = o + (size_t)(b*SEQ + s)*DIM + h*64;
        orow[lane]      = acc0 * inv;
        orow[lane + 32] = acc1 * inv;
        __syncwarp();
    }
}
#define ATTN_SMEM ((SEQ*KSTR + SEQ*HD + AW*64 + AW*224) * 4 + 256)

// ---------------- residual add + LayerNorm (writes fp32 out AND tf32 ga) ----------------
__global__ void add_ln_kernel(const float* __restrict__ x, const float* __restrict__ r,
                              const float* __restrict__ sc, const float* __restrict__ bi,
                              float* __restrict__ out, float* __restrict__ ga)
{
    __shared__ float buf[DIM];
    __shared__ float red1[8], red2[8];
    int row = blockIdx.x, tid = threadIdx.x, lane = tid & 31, w = tid >> 5;
    const float* xr = x + (size_t)row*DIM;
    const float* rr = r + (size_t)row*DIM;

    float s = 0.f;
    for (int i = tid; i < DIM; i += 256) { float v = xr[i] + rr[i]; buf[i] = v; s += v; }
    #pragma unroll
    for (int off = 16; off; off >>= 1) s += __shfl_xor_sync(0xffffffffu, s, off);
    if (lane == 0) red1[w] = s;
    __syncthreads();
    float tot = 0.f;
    #pragma unroll
    for (int i = 0; i < 8; i++) tot += red1[i];
    float mu = tot * (1.f / DIM);

    float vsum = 0.f;
    for (int i = tid; i < DIM; i += 256) { float d = buf[i] - mu; vsum += d*d; }
    #pragma unroll
    for (int off = 16; off; off >>= 1) vsum += __shfl_xor_sync(0xffffffffu, vsum, off);
    if (lane == 0) red2[w] = vsum;
    __syncthreads();
    float vtot = 0.f;
    #pragma unroll
    for (int i = 0; i < 8; i++) vtot += red2[i];
    float inv = rsqrtf(vtot * (1.f / DIM) + 1e-5f);

    float* orow = out + (size_t)row*DIM;
    float* arow = ga  + (size_t)row*DIM;
    for (int i = tid; i < DIM; i += 256) {
        float v = (buf[i] - mu) * inv * sc[i] + bi[i];
        orow[i] = v;
        arow[i] = tf32r(v);
    }
}

// ---------------- softmax: padded logits -> d_out ----------------
__global__ void softmax_rows(const float* __restrict__ in, float* __restrict__ out)
{
    int row = blockIdx.x, tid = threadIdx.x, lane = tid & 31, w = tid >> 5;
    const float* p = in + (size_t)row * NPADV;
    float* q = out + (size_t)row * VOC;
    __shared__ float smm[8], sss[8];

    float m = -INFINITY, s = 0.f;
    for (int i = tid; i < VOC; i += 256) {
        float xv = p[i];
        if (xv > m) { s = s * expf(m - xv) + 1.f; m = xv; }
        else        { s += expf(xv - m); }
    }
    #pragma unroll
    for (int off = 16; off; off >>= 1) {
        float m2 = __shfl_xor_sync(0xffffffffu, m, off);
        float s2 = __shfl_xor_sync(0xffffffffu, s, off);
        float mn = fmaxf(m, m2);
        s = s * expf(m - mn) + s2 * expf(m2 - mn);
        m = mn;
    }
    if (lane == 0) { smm[w] = m; sss[w] = s; }
    __syncthreads();
    if (tid == 0) {
        float M = smm[0], Sv = sss[0];
        #pragma unroll
        for (int i = 1; i < 8; i++) {
            float m2 = smm[i], s2 = sss[i];
            float mn = fmaxf(M, m2);
            Sv = Sv * expf(M - mn) + s2 * expf(m2 - mn);
            M = mn;
        }
        smm[0] = M; sss[0] = 1.f / Sv;
    }
    __syncthreads();
    float M = smm[0], inv = sss[0];
    for (int i = tid; i < VOC; i += 256)
        q[i] = expf(p[i] - M) * inv;
}

// ---------------- host driver ----------------
extern "C" void kernel_launch(void* const* d_in, const int* in_sizes, int n_in,
                              void* d_out, int out_size)
{
    const float* img   = (const float*)d_in[0];
    const int*   tok   = (const int*)  d_in[1];
    const int*   tmask = (const int*)  d_in[2];
    const float* temb  = (const float*)d_in[3];
    const float* sep   = (const float*)d_in[4];
    const float* Wq    = (const float*)d_in[5];
    const float* bq    = (const float*)d_in[6];
    const float* Wk    = (const float*)d_in[7];
    const float* bk    = (const float*)d_in[8];
    const float* Wv    = (const float*)d_in[9];
    const float* bv    = (const float*)d_in[10];
    const float* ln1s  = (const float*)d_in[11];
    const float* ln1b  = (const float*)d_in[12];
    const float* W1    = (const float*)d_in[13];
    const float* b1    = (const float*)d_in[14];
    const float* W2    = (const float*)d_in[15];
    const float* b2    = (const float*)d_in[16];
    const float* ln2s  = (const float*)d_in[17];
    const float* ln2b  = (const float*)d_in[18];
    const float* Wout  = (const float*)d_in[19];
    const float* bout  = (const float*)d_in[20];
    float* out = (float*)d_out;

    float *px, *pqkv, *po, *pt, *pb, *plog, *pa, *pa2, *pbt;
    cudaGetSymbolAddress((void**)&px,   g_x);
    cudaGetSymbolAddress((void**)&pqkv, g_qkv);
    cudaGetSymbolAddress((void**)&po,   g_o);
    cudaGetSymbolAddress((void**)&pt,   g_t);
    cudaGetSymbolAddress((void**)&pb,   g_b);
    cudaGetSymbolAddress((void**)&plog, g_logits);
    cudaGetSymbolAddress((void**)&pa,   g_a);
    cudaGetSymbolAddress((void**)&pa2,  g_a2);
    cudaGetSymbolAddress((void**)&pbt,  g_bt);

    cudaFuncSetAttribute(attn_kernel, cudaFuncAttributeMaxDynamicSharedMemorySize, ATTN_SMEM);
    cudaFuncSetAttribute(gemm_mma, cudaFuncAttributeMaxDynamicSharedMemorySize, DSMEM);

    embed_kernel<<<MROWS, 256>>>(img, tok, temb, sep, px, pa);

    #define GEMM(A, bias, C, K, ldc, Nreal, Npad, relu, tfo) \
        gemm_mma<<<dim3(MPAD/128, (Npad)/128), 256, DSMEM>>>(A, pbt, bias, C, K, ldc, Nreal, MROWS, relu, tfo)

    for (int l = 0; l < NL; l++) {
        const size_t woff = (size_t)l * NH * DIM * HD;
        // QKV  (A = g_a, written by embed / previous add_ln2)
        qkvw_convert<<<(QKVW*DIM + 255)/256, 256>>>(Wq + woff, Wk + woff, Wv + woff,
                                                    bq + (size_t)l*DIM, bk + (size_t)l*DIM,
                                                    bv + (size_t)l*DIM);
        GEMM(pa, pb, pqkv, DIM, QKVW, QKVW, QKVW, 0, 0);
        attn_kernel<<<BATCH*NH, 512, ATTN_SMEM>>>(pqkv, tmask, po);
        add_ln_kernel<<<MROWS, 256>>>(px, po, ln1s + (size_t)l*DIM, ln1b + (size_t)l*DIM, px, pa);
        // FFN1: writes tf32 relu output directly to g_a2
        wt_convert<<<dim3(FF/32, DIM/32), dim3(32, 8)>>>(W1 + (size_t)l*DIM*FF, DIM, FF);
        GEMM(pa, b1 + (size_t)l*FF, pa2, DIM, FF, FF, FF, 1, 1);
        // FFN2 (A = g_a2)
        wt_convert<<<dim3(DIM/32, FF/32), dim3(32, 8)>>>(W2 + (size_t)l*FF*DIM, FF, DIM);
        GEMM(pa2, b2 + (size_t)l*DIM, pt, FF, DIM, DIM, DIM, 0, 0);
        add_ln_kernel<<<MROWS, 256>>>(px, pt, ln2s + (size_t)l*DIM, ln2b + (size_t)l*DIM, px, pa);
    }

    // vocab projection (padded logits) + softmax into d_out
    wt_convert<<<dim3(NPADV/32, DIM/32), dim3(32, 8)>>>(Wout, DIM, VOC);
    GEMM(pa, bout, plog, DIM, NPADV, VOC, NPADV, 0, 0);
    softmax_rows<<<MROWS, 256>>>(plog, out);
}

// round 12
// speedup vs baseline: 1.5124x; 1.0016x over previous
#include <cuda_runtime.h>
#include <cuda_bf16.h>
#include <math.h>
#include <stdint.h>

// ---------------- problem constants ----------------
#define BATCH 16
#define IMG   197
#define TXT   24
#define SEQ   222
#define DIM   768
#define NH    12
#define HD    64
#define NL    6
#define VOC   50257
#define FF    3072
#define MROWS (BATCH*SEQ)  // 3552
#define QKVW  (3*DIM)      // 2304
#define MPAD  3584         // 28 * 128
#define NPADV 50432        // 394 * 128

// ---------------- GEMM tiling (tf32 mma.sync + ldmatrix, 3-stage) ----------------
#define TKC    32                 // K per stage (4 k8-steps)
#define ASTRF  36                 // smem row stride in floats -> conflict-free ldmatrix
#define MATSZF (128*ASTRF*4)      // 18432 B per matrix tile
#define STSZ   (2*MATSZF)         // A + B = 36864 B
#define NSTG   3
#define DSMEM  (NSTG*STSZ)        // 110592 B (x2 CTAs = 221184 < 228KB)

// ---------------- device scratch ----------------
__device__ float g_x   [MROWS*DIM];
__device__ float g_qkv [MROWS*QKVW];
__device__ float g_o   [MROWS*DIM];
__device__ float g_t   [MROWS*DIM];
__device__ float g_b   [QKVW];
__device__ float g_a   [MPAD*DIM];           // tf32 activations, K=768 GEMMs
__device__ float g_a2  [MPAD*FF];            // tf32 FFN1 output, K=3072 GEMM
__device__ float g_bt  [(size_t)NPADV*DIM];  // tf32 weights^T [Npad,K]
__device__ float g_logits[(size_t)MROWS*NPADV];

// ---------------- PTX helpers ----------------
__device__ __forceinline__ uint32_t s2u(const void* p) {
    uint32_t a;
    asm("{ .reg .u64 t; cvta.to.shared.u64 t, %1; cvt.u32.u64 %0, t; }" : "=r"(a) : "l"(p));
    return a;
}
#define CP16(dst, src)   asm volatile("cp.async.cg.shared.global [%0], [%1], 16;" :: "r"(dst), "l"(src))
#define CP_COMMIT()      asm volatile("cp.async.commit_group;" ::: "memory")
#define CP_WAIT(n)       asm volatile("cp.async.wait_group %0;" :: "n"(n) : "memory")

__device__ __forceinline__ float tf32r(float v) {
    uint32_t o;
    asm("cvt.rna.tf32.f32 %0, %1;" : "=r"(o) : "f"(v));
    return __uint_as_float(o);
}
__device__ __forceinline__ void mma_tf32(float* c, const uint32_t* a, const uint32_t* b) {
    asm volatile(
        "mma.sync.aligned.m16n8k8.row.col.f32.tf32.tf32.f32 "
        "{%0,%1,%2,%3}, {%4,%5,%6,%7}, {%8,%9}, {%0,%1,%2,%3};"
        : "+f"(c[0]), "+f"(c[1]), "+f"(c[2]), "+f"(c[3])
        : "r"(a[0]), "r"(a[1]), "r"(a[2]), "r"(a[3]), "r"(b[0]), "r"(b[1]));
}
__device__ __forceinline__ void ldsm4(uint32_t* r, uint32_t addr) {
    asm volatile("ldmatrix.sync.aligned.m8n8.x4.shared.b16 {%0,%1,%2,%3}, [%4];"
                 : "=r"(r[0]), "=r"(r[1]), "=r"(r[2]), "=r"(r[3]) : "r"(addr));
}

// ---------------- embedding (writes fp32 x AND tf32 g_a) ----------------
__global__ void embed_kernel(const float* __restrict__ img, const int* __restrict__ tok,
                             const float* __restrict__ temb, const float* __restrict__ sep,
                             float* __restrict__ x, float* __restrict__ ga)
{
    int row = blockIdx.x;
    int b = row / SEQ, s = row % SEQ;
    const float* src;
    if (s < IMG)       src = img + (size_t)(b*IMG + s)*DIM;
    else if (s == IMG) src = sep;
    else               src = temb + (size_t)tok[b*TXT + (s-IMG-1)] * DIM;
    float* dst = x + (size_t)row*DIM;
    float* da  = ga + (size_t)row*DIM;
    for (int i = threadIdx.x; i < DIM; i += blockDim.x) {
        float v = src[i];
        dst[i] = v;
        da[i]  = tf32r(v);
    }
}

// ---------------- weight transpose+round ----------------
__global__ void wt_convert(const float* __restrict__ src, int K, int N)
{
    __shared__ float t[32][33];
    int n0 = blockIdx.x*32, k0 = blockIdx.y*32;
    int tx = threadIdx.x, ty = threadIdx.y;
    #pragma unroll
    for (int j = 0; j < 32; j += 8) {
        int n = n0 + tx;
        t[ty+j][tx] = (n < N) ? src[(size_t)(k0+ty+j)*N + n] : 0.f;
    }
    __syncthreads();
    #pragma unroll
    for (int j = 0; j < 32; j += 8) {
        int n = n0 + ty + j, k = k0 + tx;
        g_bt[(size_t)n*K + k] = tf32r(t[tx][ty+j]);
    }
}

// ---------------- QKV weight gather+round ----------------
__global__ void qkvw_convert(const float* __restrict__ Wq, const float* __restrict__ Wk,
                             const float* __restrict__ Wv,
                             const float* __restrict__ bq, const float* __restrict__ bk,
                             const float* __restrict__ bv)
{
    int idx = blockIdx.x*256 + threadIdx.x;
    if (idx < QKVW*DIM) {
        int c = idx / DIM, d = idx % DIM;
        int which = c / DIM, w2 = c % DIM;
        int h = w2 >> 6, e = w2 & 63;
        const float* W = (which == 0) ? Wq : (which == 1) ? Wk : Wv;
        g_bt[idx] = tf32r(W[(size_t)h*DIM*HD + (size_t)d*HD + e]);
    }
    if (idx < QKVW) {
        int which = idx / DIM, cc = idx % DIM;
        const float* bb = (which == 0) ? bq : (which == 1) ? bk : bv;
        g_b[idx] = bb[cc];
    }
}

// ---------------- tf32 mma.sync GEMM, 3-stage cp.async, ldmatrix frags ----------------
__global__ __launch_bounds__(256, 2)
void gemm_mma(const float* __restrict__ Aa, const float* __restrict__ Bt,
              const float* __restrict__ bias, float* __restrict__ C,
              int K, int ldc, int Nreal, int Mreal, int relu, int tf32out)
{
    extern __shared__ char dsm[];
    const int tid = threadIdx.x;
    const int wid = tid >> 5, lane = tid & 31;
    const int m0 = blockIdx.x * 128, n0 = blockIdx.y * 128;
    const int wm = wid >> 2, wn = wid & 3;
    const int g = lane >> 2, t = lane & 3;
    const int nk = K / TKC;
    const uint32_t sb = s2u(dsm);

    const uint32_t aLaneOff =
        (uint32_t)(((wm*64 + ((lane & 8) ? 8 : 0) + (lane & 7)) * ASTRF)
                   + ((lane & 16) ? 4 : 0)) * 4;
    const uint32_t bLaneOff =
        (uint32_t)(((wn*32 + ((lane & 16) ? 8 : 0) + (lane & 7)) * ASTRF)
                   + ((lane & 8) ? 4 : 0)) * 4;

    float acc[4][4][4];
    #pragma unroll
    for (int mi = 0; mi < 4; mi++)
        #pragma unroll
        for (int ni = 0; ni < 4; ni++)
            #pragma unroll
            for (int r = 0; r < 4; r++) acc[mi][ni][r] = 0.f;

    #define LOAD_ST(st, kc) do {                                                     \
        int k0_ = (kc) * TKC;                                                        \
        _Pragma("unroll")                                                            \
        for (int c_ = tid; c_ < 2048; c_ += 256) {                                   \
            int isB_ = (c_ >= 1024);                                                 \
            int cc_  = c_ & 1023;                                                    \
            int row_ = cc_ >> 3, c4_ = cc_ & 7;                                      \
            const float* sp_ = (isB_ ? Bt + (size_t)(n0 + row_) * K                  \
                                     : Aa + (size_t)(m0 + row_) * K) + k0_ + c4_*4;  \
            uint32_t dst_ = sb + (st)*STSZ + (isB_ ? MATSZF : 0) + row_*144 + c4_*16;\
            CP16(dst_, sp_);                                                         \
        }                                                                            \
        CP_COMMIT();                                                                 \
    } while (0)

    LOAD_ST(0, 0);
    LOAD_ST(1, 1);

    int cur = 0, nx2 = 2;
    for (int kc = 0; kc < nk; kc++) {
        if (kc < nk - 1) CP_WAIT(1); else CP_WAIT(0);
        __syncthreads();
        if (kc + 2 < nk) LOAD_ST(nx2, kc + 2);

        const uint32_t stg = sb + cur*STSZ;
        const uint32_t aB = stg + aLaneOff;
        const uint32_t bB = stg + MATSZF + bLaneOff;

        #pragma unroll
        for (int ks = 0; ks < 4; ks++) {
            const uint32_t kof = ks * 32;
            uint32_t af[16], bf[16];
            #pragma unroll
            for (int mi = 0; mi < 4; mi++)
                ldsm4(af + mi*4, aB + mi*(16*ASTRF*4) + kof);
            ldsm4(bf,     bB + kof);
            ldsm4(bf + 4, bB + 16*ASTRF*4 + kof);
            #pragma unroll
            for (int mi = 0; mi < 4; mi++) {
                #pragma unroll
                for (int ni = 0; ni < 4; ni++)
                    mma_tf32(acc[mi][ni], af + mi*4, bf + ni*2);
            }
        }
        cur = (cur == 2) ? 0 : cur + 1;
        nx2 = (nx2 == 2) ? 0 : nx2 + 1;
    }

    #pragma unroll
    for (int mi = 0; mi < 4; mi++) {
        int gm0 = m0 + wm*64 + mi*16 + g;
        #pragma unroll
        for (int ni = 0; ni < 4; ni++) {
            int gn = n0 + wn*32 + ni*8 + t*2;
            float bx = (gn     < Nreal) ? bias[gn]     : 0.f;
            float by = (gn + 1 < Nreal) ? bias[gn + 1] : 0.f;
            float c0 = acc[mi][ni][0] + bx, c1 = acc[mi][ni][1] + by;
            float c2 = acc[mi][ni][2] + bx, c3 = acc[mi][ni][3] + by;
            if (relu) {
                c0 = fmaxf(c0, 0.f); c1 = fmaxf(c1, 0.f);
                c2 = fmaxf(c2, 0.f); c3 = fmaxf(c3, 0.f);
            }
            if (tf32out) {
                c0 = tf32r(c0); c1 = tf32r(c1); c2 = tf32r(c2); c3 = tf32r(c3);
            }
            if (gm0 < Mreal)
                *reinterpret_cast<float2*>(C + (size_t)gm0*ldc + gn) = make_float2(c0, c1);
            if (gm0 + 8 < Mreal)
                *reinterpret_cast<float2*>(C + (size_t)(gm0+8)*ldc + gn) = make_float2(c2, c3);
        }
    }
}

// ---------------- attention: 1 block per (b,h), 16 warps x 2 query rows ----------------
// Pairing adjacent rows (s0, s0+1) per warp: each K/V smem load feeds BOTH rows,
// halving crossbar traffic per FMA (the R11 bottleneck).
#define KSTR 65
#define AW   16
__global__ __launch_bounds__(512, 1)
void attn_kernel(const float* __restrict__ qkv,
                 const int* __restrict__ tmask,
                 float* __restrict__ o)
{
    int b = blockIdx.x / NH, h = blockIdx.x % NH;
    extern __shared__ float sm[];
    float* ks = sm;                         // SEQ*65
    float* vs = ks + SEQ*KSTR;              // SEQ*64
    float* qs = vs + SEQ*HD;                // 32*64  (2 rows per warp)
    float* sc = qs + AW*2*64;               // 32*224
    unsigned char* valid = (unsigned char*)(sc + AW*2*224);

    int tid = threadIdx.x, lane = tid & 31, w = tid >> 5;
    const float* base = qkv + (size_t)b * SEQ * QKVW;

    for (int i = tid; i < SEQ*HD; i += 512) {
        int t = i >> 6, e = i & 63;
        ks[t*KSTR + e] = base[(size_t)t*QKVW +   DIM + h*64 + e];
        vs[t*HD   + e] = base[(size_t)t*QKVW + 2*DIM + h*64 + e];
    }
    for (int t = tid; t < SEQ; t += 512)
        valid[t] = (t < SEQ - TXT) ? 1 : (tmask[b*TXT + t - (SEQ-TXT)] != 0);
    __syncthreads();

    float* qa  = qs + (2*w)*64;   float* qb  = qa + 64;
    float* sca = sc + (2*w)*224;  float* scb = sca + 224;

    for (int s0 = 2*w; s0 < SEQ; s0 += 2*AW) {
        const int sa = s0, sb2 = s0 + 1;    // sb2 <= 221 always (s0 even <= 220)
        qa[lane]      = base[(size_t)sa*QKVW  + h*64 + lane];
        qa[lane + 32] = base[(size_t)sa*QKVW  + h*64 + lane + 32];
        qb[lane]      = base[(size_t)sb2*QKVW + h*64 + lane];
        qb[lane + 32] = base[(size_t)sb2*QKVW + h*64 + lane + 32];
        __syncwarp();

        const int jn = (sb2 >= lane) ? ((sb2 - lane) >> 5) + 1 : 0;   // t = lane+32j <= sb2
        float da[7], db[7];
        #pragma unroll
        for (int j = 0; j < 7; j++) { da[j] = 0.f; db[j] = 0.f; }

        for (int e0 = 0; e0 < 64; e0 += 4) {
            float qa0 = qa[e0], qa1 = qa[e0+1], qa2 = qa[e0+2], qa3 = qa[e0+3];
            float qb0 = qb[e0], qb1 = qb[e0+1], qb2 = qb[e0+2], qb3 = qb[e0+3];
            #pragma unroll 7
            for (int j = 0; j < jn; j++) {
                const float* kr = ks + (lane + 32*j)*KSTR + e0;
                float k0 = kr[0], k1 = kr[1], k2 = kr[2], k3 = kr[3];
                da[j] += qa0*k0 + qa1*k1 + qa2*k2 + qa3*k3;
                db[j] += qb0*k0 + qb1*k1 + qb2*k2 + qb3*k3;
            }
        }

        // store scores (mask) + per-row max in-register
        float ma = -INFINITY, mb = -INFINITY;
        #pragma unroll 7
        for (int j = 0; j < jn; j++) {
            int t = lane + 32*j;
            float vb = valid[t] ? db[j]*0.125f : -INFINITY;
            scb[t] = vb; mb = fmaxf(mb, vb);
            if (t <= sa) {
                float va = valid[t] ? da[j]*0.125f : -INFINITY;
                sca[t] = va; ma = fmaxf(ma, va);
            }
        }
        #pragma unroll
        for (int off = 16; off; off >>= 1) {
            ma = fmaxf(ma, __shfl_xor_sync(0xffffffffu, ma, off));
            mb = fmaxf(mb, __shfl_xor_sync(0xffffffffu, mb, off));
        }

        // exp + sums
        float sua = 0.f, sub = 0.f;
        #pragma unroll 7
        for (int j = 0; j < jn; j++) {
            int t = lane + 32*j;
            float pb = expf(scb[t] - mb); scb[t] = pb; sub += pb;
            if (t <= sa) { float pa = expf(sca[t] - ma); sca[t] = pa; sua += pa; }
        }
        #pragma unroll
        for (int off = 16; off; off >>= 1) {
            sua += __shfl_xor_sync(0xffffffffu, sua, off);
            sub += __shfl_xor_sync(0xffffffffu, sub, off);
        }
        float inva = 1.f / sua, invb = 1.f / sub;
        __syncwarp();

        // PV: shared V loads feed both rows
        float a0 = 0.f, a1 = 0.f, b0 = 0.f, b1 = 0.f;
        for (int t = 0; t <= sa; t++) {
            float pa = sca[t], pb = scb[t];
            float v0 = vs[t*HD + lane], v1 = vs[t*HD + lane + 32];
            a0 += pa*v0; a1 += pa*v1;
            b0 += pb*v0; b1 += pb*v1;
        }
        {   // tail: t = sb2 contributes to row b only
            float pb = scb[sb2];
            b0 += pb * vs[sb2*HD + lane];
            b1 += pb * vs[sb2*HD + lane + 32];
        }
        float* ra = o + (size_t)(b*SEQ + sa)*DIM + h*64;
        ra[lane]      = a0 * inva;
        ra[lane + 32] = a1 * inva;
        float* rb = o + (size_t)(b*SEQ + sb2)*DIM + h*64;
        rb[lane]      = b0 * invb;
        rb[lane + 32] = b1 * invb;
        __syncwarp();
    }
}
#define ATTN_SMEM ((SEQ*KSTR + SEQ*HD + AW*2*64 + AW*2*224) * 4 + 256)

// ---------------- residual add + LayerNorm (writes fp32 out AND tf32 ga) ----------------
__global__ void add_ln_kernel(const float* __restrict__ x, const float* __restrict__ r,
                              const float* __restrict__ sc, const float* __restrict__ bi,
                              float* __restrict__ out, float* __restrict__ ga)
{
    __shared__ float buf[DIM];
    __shared__ float red1[8], red2[8];
    int row = blockIdx.x, tid = threadIdx.x, lane = tid & 31, w = tid >> 5;
    const float* xr = x + (size_t)row*DIM;
    const float* rr = r + (size_t)row*DIM;

    float s = 0.f;
    for (int i = tid; i < DIM; i += 256) { float v = xr[i] + rr[i]; buf[i] = v; s += v; }
    #pragma unroll
    for (int off = 16; off; off >>= 1) s += __shfl_xor_sync(0xffffffffu, s, off);
    if (lane == 0) red1[w] = s;
    __syncthreads();
    float tot = 0.f;
    #pragma unroll
    for (int i = 0; i < 8; i++) tot += red1[i];
    float mu = tot * (1.f / DIM);

    float vsum = 0.f;
    for (int i = tid; i < DIM; i += 256) { float d = buf[i] - mu; vsum += d*d; }
    #pragma unroll
    for (int off = 16; off; off >>= 1) vsum += __shfl_xor_sync(0xffffffffu, vsum, off);
    if (lane == 0) red2[w] = vsum;
    __syncthreads();
    float vtot = 0.f;
    #pragma unroll
    for (int i = 0; i < 8; i++) vtot += red2[i];
    float inv = rsqrtf(vtot * (1.f / DIM) + 1e-5f);

    float* orow = out + (size_t)row*DIM;
    float* arow = ga  + (size_t)row*DIM;
    for (int i = tid; i < DIM; i += 256) {
        float v = (buf[i] - mu) * inv * sc[i] + bi[i];
        orow[i] = v;
        arow[i] = tf32r(v);
    }
}

// ---------------- softmax: padded logits -> d_out ----------------
__global__ void softmax_rows(const float* __restrict__ in, float* __restrict__ out)
{
    int row = blockIdx.x, tid = threadIdx.x, lane = tid & 31, w = tid >> 5;
    const float* p = in + (size_t)row * NPADV;
    float* q = out + (size_t)row * VOC;
    __shared__ float smm[8], sss[8];

    float m = -INFINITY, s = 0.f;
    for (int i = tid; i < VOC; i += 256) {
        float xv = p[i];
        if (xv > m) { s = s * expf(m - xv) + 1.f; m = xv; }
        else        { s += expf(xv - m); }
    }
    #pragma unroll
    for (int off = 16; off; off >>= 1) {
        float m2 = __shfl_xor_sync(0xffffffffu, m, off);
        float s2 = __shfl_xor_sync(0xffffffffu, s, off);
        float mn = fmaxf(m, m2);
        s = s * expf(m - mn) + s2 * expf(m2 - mn);
        m = mn;
    }
    if (lane == 0) { smm[w] = m; sss[w] = s; }
    __syncthreads();
    if (tid == 0) {
        float M = smm[0], Sv = sss[0];
        #pragma unroll
        for (int i = 1; i < 8; i++) {
            float m2 = smm[i], s2 = sss[i];
            float mn = fmaxf(M, m2);
            Sv = Sv * expf(M - mn) + s2 * expf(m2 - mn);
            M = mn;
        }
        smm[0] = M; sss[0] = 1.f / Sv;
    }
    __syncthreads();
    float M = smm[0], inv = sss[0];
    for (int i = tid; i < VOC; i += 256)
        q[i] = expf(p[i] - M) * inv;
}

// ---------------- host driver ----------------
extern "C" void kernel_launch(void* const* d_in, const int* in_sizes, int n_in,
                              void* d_out, int out_size)
{
    const float* img   = (const float*)d_in[0];
    const int*   tok   = (const int*)  d_in[1];
    const int*   tmask = (const int*)  d_in[2];
    const float* temb  = (const float*)d_in[3];
    const float* sep   = (const float*)d_in[4];
    const float* Wq    = (const float*)d_in[5];
    const float* bq    = (const float*)d_in[6];
    const float* Wk    = (const float*)d_in[7];
    const float* bk    = (const float*)d_in[8];
    const float* Wv    = (const float*)d_in[9];
    const float* bv    = (const float*)d_in[10];
    const float* ln1s  = (const float*)d_in[11];
    const float* ln1b  = (const float*)d_in[12];
    const float* W1    = (const float*)d_in[13];
    const float* b1    = (const float*)d_in[14];
    const float* W2    = (const float*)d_in[15];
    const float* b2    = (const float*)d_in[16];
    const float* ln2s  = (const float*)d_in[17];
    const float* ln2b  = (const float*)d_in[18];
    const float* Wout  = (const float*)d_in[19];
    const float* bout  = (const float*)d_in[20];
    float* out = (float*)d_out;

    float *px, *pqkv, *po, *pt, *pb, *plog, *pa, *pa2, *pbt;
    cudaGetSymbolAddress((void**)&px,   g_x);
    cudaGetSymbolAddress((void**)&pqkv, g_qkv);
    cudaGetSymbolAddress((void**)&po,   g_o);
    cudaGetSymbolAddress((void**)&pt,   g_t);
    cudaGetSymbolAddress((void**)&pb,   g_b);
    cudaGetSymbolAddress((void**)&plog, g_logits);
    cudaGetSymbolAddress((void**)&pa,   g_a);
    cudaGetSymbolAddress((void**)&pa2,  g_a2);
    cudaGetSymbolAddress((void**)&pbt,  g_bt);

    cudaFuncSetAttribute(attn_kernel, cudaFuncAttributeMaxDynamicSharedMemorySize, ATTN_SMEM);
    cudaFuncSetAttribute(gemm_mma, cudaFuncAttributeMaxDynamicSharedMemorySize, DSMEM);

    embed_kernel<<<MROWS, 256>>>(img, tok, temb, sep, px, pa);

    #define GEMM(A, bias, C, K, ldc, Nreal, Npad, relu, tfo) \
        gemm_mma<<<dim3(MPAD/128, (Npad)/128), 256, DSMEM>>>(A, pbt, bias, C, K, ldc, Nreal, MROWS, relu, tfo)

    for (int l = 0; l < NL; l++) {
        const size_t woff = (size_t)l * NH * DIM * HD;
        // QKV  (A = g_a, written by embed / previous add_ln2)
        qkvw_convert<<<(QKVW*DIM + 255)/256, 256>>>(Wq + woff, Wk + woff, Wv + woff,
                                                    bq + (size_t)l*DIM, bk + (size_t)l*DIM,
                                                    bv + (size_t)l*DIM);
        GEMM(pa, pb, pqkv, DIM, QKVW, QKVW, QKVW, 0, 0);
        attn_kernel<<<BATCH*NH, 512, ATTN_SMEM>>>(pqkv, tmask, po);
        add_ln_kernel<<<MROWS, 256>>>(px, po, ln1s + (size_t)l*DIM, ln1b + (size_t)l*DIM, px, pa);
        // FFN1: writes tf32 relu output directly to g_a2
        wt_convert<<<dim3(FF/32, DIM/32), dim3(32, 8)>>>(W1 + (size_t)l*DIM*FF, DIM, FF);
        GEMM(pa, b1 + (size_t)l*FF, pa2, DIM, FF, FF, FF, 1, 1);
        // FFN2 (A = g_a2)
        wt_convert<<<dim3(DIM/32, FF/32), dim3(32, 8)>>>(W2 + (size_t)l*FF*DIM, FF, DIM);
        GEMM(pa2, b2 + (size_t)l*DIM, pt, FF, DIM, DIM, DIM, 0, 0);
        add_ln_kernel<<<MROWS, 256>>>(px, pt, ln2s + (size_t)l*DIM, ln2b + (size_t)l*DIM, px, pa);
    }

    // vocab projection (padded logits) + softmax into d_out
    wt_convert<<<dim3(NPADV/32, DIM/32), dim3(32, 8)>>>(Wout, DIM, VOC);
    GEMM(pa, bout, plog, DIM, NPADV, VOC, NPADV, 0, 0);
    softmax_rows<<<MROWS, 256>>>(plog, out);
}